// round 5
// baseline (speedup 1.0000x reference)
#include <cuda_runtime.h>
#include <math.h>
#include <float.h>

#define B_   32
#define NF_  196
#define ENC_ 2048
#define V_   32000
#define ED_  512
#define S_   32
#define H_   1024
#define NB_  128        // persistent grid size (all co-resident on 148 SMs)

// ---------------- f32x2 packed helpers (sm_103a) -----------------------------
__device__ __forceinline__ void fma2(unsigned long long& d,
                                     unsigned long long a, unsigned long long b) {
    asm("fma.rn.f32x2 %0, %1, %2, %0;" : "+l"(d) : "l"(a), "l"(b));
}
__device__ __forceinline__ unsigned long long pack2(float lo, float hi) {
    unsigned long long r;
    asm("mov.b64 %0, {%1, %2};" : "=l"(r) : "f"(lo), "f"(hi));
    return r;
}
__device__ __forceinline__ float2 unpk2(unsigned long long v) {
    float2 r;
    asm("mov.b64 {%0, %1}, %2;" : "=f"(r.x), "=f"(r.y) : "l"(v));
    return r;
}

// ---------------- scratch ----------------------------------------------------
static constexpr size_t SZ_K    = (size_t)B_ * NF_ * H_;
static constexpr size_t OFF_K   = 0;
static constexpr size_t OFF_V   = OFF_K + SZ_K;
static constexpr size_t OFF_MEAN= OFF_V + SZ_K;
static constexpr size_t OFF_H   = OFF_MEAN + (size_t)B_ * ENC_;
static constexpr size_t OFF_C   = OFF_H   + (size_t)B_ * H_;
static constexpr size_t OFF_Q   = OFF_C   + (size_t)B_ * H_;
static constexpr size_t OFF_CTX = OFF_Q   + (size_t)B_ * H_;
static constexpr size_t OFF_O   = OFF_CTX + (size_t)B_ * H_;
static constexpr size_t OFF_EMB = OFF_O   + (size_t)B_ * H_;
static constexpr size_t OFF_XP  = OFF_EMB + (size_t)B_ * S_ * ED_;
static constexpr size_t OFF_HALL= OFF_XP  + (size_t)B_ * S_ * 4 * H_;
static constexpr size_t OFF_AD  = OFF_HALL+ (size_t)B_ * S_ * H_;
static constexpr size_t TOTAL_F = OFF_AD  + (size_t)B_ * S_ * NF_;

__device__ float g_scratch[TOTAL_F];
__device__ unsigned g_bar_count = 0;
__device__ unsigned g_bar_gen   = 0;

// ---------------- grid-wide barrier ------------------------------------------
__device__ __forceinline__ void grid_bar() {
    __syncthreads();
    if (threadIdx.x == 0) {
        __threadfence();
        unsigned gen = *(volatile unsigned*)&g_bar_gen;
        unsigned a = atomicAdd(&g_bar_count, 1u);
        if (a == NB_ - 1) {
            atomicExch(&g_bar_count, 0u);
            __threadfence();
            atomicAdd(&g_bar_gen, 1u);
        } else {
            while (*(volatile unsigned*)&g_bar_gen == gen) { }
        }
        __threadfence();
    }
    __syncthreads();
}

// ---------------- mean over N + exact gelu -----------------------------------
__global__ __launch_bounds__(256) void mean_gelu_kernel(
    const float* __restrict__ feat, float* __restrict__ outMean)
{
    int b = blockIdx.y;
    int e = blockIdx.x * 256 + threadIdx.x;
    const float* p = feat + (size_t)b * NF_ * ENC_ + e;
    float s = 0.f;
    #pragma unroll 4
    for (int n = 0; n < NF_; n++) s += p[(size_t)n * ENC_];
    s *= (1.0f / (float)NF_);
    outMean[(size_t)b * ENC_ + e] = 0.5f * s * (1.0f + erff(s * 0.70710678118654752f));
}

// ---------------- embedding gather -------------------------------------------
__global__ __launch_bounds__(256) void gather_kernel(
    const float* __restrict__ emb, const int* __restrict__ cap,
    float* __restrict__ out)
{
    int idx = blockIdx.x * 256 + threadIdx.x;
    int d  = idx & (ED_ - 1);
    int bs = idx >> 9;
    out[idx] = emb[(size_t)cap[bs] * ED_ + d];
}

// ---------------- batched GEMV for M=32 (setup h0/c0 only) -------------------
__global__ __launch_bounds__(256) void gemvM32(
    const float* __restrict__ A, const float* __restrict__ W,
    const float* __restrict__ bias, float* __restrict__ C, int ldc, int K)
{
    __shared__ float sA[32][64];
    int tid = threadIdx.x, lane = tid & 31, w = tid >> 5;
    int n = blockIdx.x * 8 + w;
    const float* Wn = W + (size_t)n * K;
    float acc[32];
    #pragma unroll
    for (int b = 0; b < 32; b++) acc[b] = 0.f;
    for (int k0 = 0; k0 < K; k0 += 64) {
        __syncthreads();
        int kk = tid & 63, bb = tid >> 6;
        #pragma unroll
        for (int i = 0; i < 8; i++)
            sA[bb + i * 4][kk] = A[(size_t)(bb + i * 4) * K + k0 + kk];
        __syncthreads();
        float w0 = Wn[k0 + lane], w1 = Wn[k0 + 32 + lane];
        #pragma unroll
        for (int b = 0; b < 32; b++)
            acc[b] += w0 * sA[b][lane] + w1 * sA[b][lane + 32];
    }
    float out = 0.f;
    #pragma unroll
    for (int b = 0; b < 32; b++) {
        float v = acc[b];
        #pragma unroll
        for (int o = 16; o; o >>= 1) v += __shfl_xor_sync(0xffffffffu, v, o);
        if (lane == b) out = v;
    }
    C[(size_t)lane * (size_t)ldc + n] = out + bias[n];
}

// ---------------- 128x128 SGEMM, double-buffered, f32x2 ----------------------
__device__ __forceinline__ void g128_compute(
    const float (*cA)[132], const float (*cB)[132],
    int tx, int ty, unsigned long long acc2[8][4])
{
    #pragma unroll
    for (int k = 0; k < 16; k++) {
        float ar[8];
        *(float4*)&ar[0] = *(const float4*)&cA[k][ty * 8];
        *(float4*)&ar[4] = *(const float4*)&cA[k][ty * 8 + 4];
        const unsigned long long* pb = (const unsigned long long*)&cB[k][tx * 8];
        unsigned long long bb0 = pb[0], bb1 = pb[1], bb2 = pb[2], bb3 = pb[3];
        #pragma unroll
        for (int i = 0; i < 8; i++) {
            unsigned long long aa = pack2(ar[i], ar[i]);
            fma2(acc2[i][0], aa, bb0);
            fma2(acc2[i][1], aa, bb1);
            fma2(acc2[i][2], aa, bb2);
            fma2(acc2[i][3], aa, bb3);
        }
    }
}

__global__ __launch_bounds__(256, 2) void gemm128(
    const float* __restrict__ A, int lda,
    const float* __restrict__ W,          // [N,K]
    const float* __restrict__ bias,
    float* __restrict__ C, int ldc, int K)
{
    __shared__ float sA[2][16][132];
    __shared__ float sB[2][16][132];
    int tid = threadIdx.x;
    int m0 = blockIdx.y * 128, n0 = blockIdx.x * 128;
    int lr = tid >> 2, lk = (tid & 3) * 4;
    const float* Ab = A + (size_t)m0 * lda + lk;
    const float* Wb = W + (size_t)n0 * K + lk;
    int tx = tid & 15, ty = tid >> 4;

    unsigned long long acc2[8][4];
    #pragma unroll
    for (int i = 0; i < 8; i++)
        #pragma unroll
        for (int j = 0; j < 4; j++) acc2[i][j] = 0ull;

    // prologue: tile 0 -> buf 0
    {
        float4 a0 = *(const float4*)(Ab + (size_t)lr * lda);
        float4 a1 = *(const float4*)(Ab + (size_t)(lr + 64) * lda);
        float4 b0 = *(const float4*)(Wb + (size_t)lr * K);
        float4 b1 = *(const float4*)(Wb + (size_t)(lr + 64) * K);
        sA[0][lk+0][lr]=a0.x; sA[0][lk+1][lr]=a0.y; sA[0][lk+2][lr]=a0.z; sA[0][lk+3][lr]=a0.w;
        sA[0][lk+0][lr+64]=a1.x; sA[0][lk+1][lr+64]=a1.y; sA[0][lk+2][lr+64]=a1.z; sA[0][lk+3][lr+64]=a1.w;
        sB[0][lk+0][lr]=b0.x; sB[0][lk+1][lr]=b0.y; sB[0][lk+2][lr]=b0.z; sB[0][lk+3][lr]=b0.w;
        sB[0][lk+0][lr+64]=b1.x; sB[0][lk+1][lr+64]=b1.y; sB[0][lk+2][lr+64]=b1.z; sB[0][lk+3][lr+64]=b1.w;
    }
    __syncthreads();
    int buf = 0;
    for (int k0 = 16; k0 < K; k0 += 16) {
        float4 na0 = *(const float4*)(Ab + (size_t)lr * lda + k0);
        float4 na1 = *(const float4*)(Ab + (size_t)(lr + 64) * lda + k0);
        float4 nb0 = *(const float4*)(Wb + (size_t)lr * K + k0);
        float4 nb1 = *(const float4*)(Wb + (size_t)(lr + 64) * K + k0);
        g128_compute(sA[buf], sB[buf], tx, ty, acc2);
        int nb = buf ^ 1;
        sA[nb][lk+0][lr]=na0.x; sA[nb][lk+1][lr]=na0.y; sA[nb][lk+2][lr]=na0.z; sA[nb][lk+3][lr]=na0.w;
        sA[nb][lk+0][lr+64]=na1.x; sA[nb][lk+1][lr+64]=na1.y; sA[nb][lk+2][lr+64]=na1.z; sA[nb][lk+3][lr+64]=na1.w;
        sB[nb][lk+0][lr]=nb0.x; sB[nb][lk+1][lr]=nb0.y; sB[nb][lk+2][lr]=nb0.z; sB[nb][lk+3][lr]=nb0.w;
        sB[nb][lk+0][lr+64]=nb1.x; sB[nb][lk+1][lr+64]=nb1.y; sB[nb][lk+2][lr+64]=nb1.z; sB[nb][lk+3][lr+64]=nb1.w;
        __syncthreads();
        buf = nb;
    }
    g128_compute(sA[buf], sB[buf], tx, ty, acc2);

    int n = n0 + tx * 8;
    float bb[8] = {0.f,0.f,0.f,0.f,0.f,0.f,0.f,0.f};
    if (bias) {
        *(float4*)&bb[0] = *(const float4*)(bias + n);
        *(float4*)&bb[4] = *(const float4*)(bias + n + 4);
    }
    #pragma unroll
    for (int i = 0; i < 8; i++) {
        size_t m = (size_t)(m0 + ty * 8 + i);
        float2 v0 = unpk2(acc2[i][0]);
        float2 v1 = unpk2(acc2[i][1]);
        float2 v2 = unpk2(acc2[i][2]);
        float2 v3 = unpk2(acc2[i][3]);
        float4 r0 = make_float4(v0.x+bb[0], v0.y+bb[1], v1.x+bb[2], v1.y+bb[3]);
        float4 r1 = make_float4(v2.x+bb[4], v2.y+bb[5], v3.x+bb[6], v3.y+bb[7]);
        *(float4*)(C + m * (size_t)ldc + n)     = r0;
        *(float4*)(C + m * (size_t)ldc + n + 4) = r1;
    }
}

// ---------------- persistent recurrence kernel -------------------------------
// Dynamic smem (floats): SQW[8192] SOW[8192] SWH[32768] SST[32*132=4224]
extern __shared__ float dsm[];

// warp computes 4 batches x 8 cols; x staged per 128-k chunk into SST (pitch 132)
__device__ __forceinline__ void gemv8(
    const float* __restrict__ Ag,      // [32,1024] global x
    const float* sW,                   // 8 cols x 1024, row-major
    float* SST,
    const float* __restrict__ bias, int n0,
    const float* __restrict__ addH,    // optional: out += addH[b][n]
    float* __restrict__ Cg, int tid)
{
    int lane = tid & 31, w = tid >> 5;
    unsigned long long acc[32];        // [b_local*8 + n]
    #pragma unroll
    for (int p = 0; p < 32; p++) acc[p] = 0ull;

    #pragma unroll 1
    for (int k0 = 0; k0 < H_; k0 += 128) {
        __syncthreads();
        {
            int sb = tid >> 3, sl = tid & 7;
            const float* src = Ag + (size_t)sb * H_ + k0 + sl * 4;
            float* dst = SST + sb * 132 + sl * 4;
            #pragma unroll
            for (int i = 0; i < 4; i++)
                *(float4*)(dst + i * 32) = *(const float4*)(src + i * 32);
        }
        __syncthreads();
        ulonglong2 xp[4];
        #pragma unroll
        for (int b = 0; b < 4; b++)
            xp[b] = *(const ulonglong2*)&SST[(4 * w + b) * 132 + 4 * lane];
        #pragma unroll
        for (int n = 0; n < 8; n++) {
            ulonglong2 wv = *(const ulonglong2*)&sW[n * H_ + k0 + 4 * lane];
            #pragma unroll
            for (int b = 0; b < 4; b++) {
                fma2(acc[b * 8 + n], xp[b].x, wv.x);
                fma2(acc[b * 8 + n], xp[b].y, wv.y);
            }
        }
    }
    float outv = 0.f;
    #pragma unroll
    for (int p = 0; p < 32; p++) {
        float2 v = unpk2(acc[p]);
        float s = v.x + v.y;
        #pragma unroll
        for (int o = 16; o; o >>= 1) s += __shfl_xor_sync(0xffffffffu, s, o);
        if (lane == p) outv = s;
    }
    int bg = 4 * w + (lane >> 3);
    int ng = n0 + (lane & 7);
    float r = outv + bias[ng];
    if (addH) r += addH[(size_t)bg * H_ + ng];
    Cg[(size_t)bg * H_ + ng] = r;
}

__global__ __launch_bounds__(256, 1) void recurrence_kernel(
    const float* __restrict__ q_w,  const float* __restrict__ in_b,
    const float* __restrict__ out_w,const float* __restrict__ out_b,
    const float* __restrict__ w_hh, const float* __restrict__ b_hh,
    const float* __restrict__ ln_g, const float* __restrict__ ln_b2,
    const float* __restrict__ gK,   const float* __restrict__ gV,
    const float* __restrict__ gXp,
    float* gH, float* gC, float* gQ,
    float* gCtx, float* gO, float* gHall, float* attnb)
{
    __shared__ float sScore[224];
    __shared__ float sProb[224];
    __shared__ float sred[8];
    __shared__ float sbc;
    __shared__ float sG[1024];
    __shared__ float sMu[32], sRs[32];

    float* SQW = dsm;
    float* SOW = dsm + 8192;
    float* SWH = dsm + 16384;
    float* SST = dsm + 49152;

    int tid = threadIdx.x, lane = tid & 31, w = tid >> 5;
    int bx = blockIdx.x;

    // ---- one-time weight preload ----
    for (int i = tid; i < 8192; i += 256) {
        SQW[i] = q_w [(size_t)bx * 8192 + i];
        SOW[i] = out_w[(size_t)bx * 8192 + i];
    }
    for (int g = 0; g < 4; g++)
        for (int i = tid; i < 8192; i += 256)
            SWH[g * 8192 + i] = w_hh[((size_t)g * H_ + bx * 8) * H_ + i];
    __syncthreads();

    for (int t = 0; t < S_; t++) {
        // ---- P0: q = h @ q_w^T + in_b[:H] ----
        gemv8(gH, SQW, SST, in_b, bx * 8, nullptr, gQ, tid);
        grid_bar();

        // ---- P1: fused scores + softmax + ctx (blocks 0..31) ----
        if (bx < 32) {
            int b = bx;
            for (int i = tid; i < 256; i += 256)
                *(float4*)&SST[i * 4] = *(const float4*)(gQ + (size_t)b * H_ + i * 4);
            __syncthreads();
            // scores: 2 n per warp per iteration (MLP=16)
            #pragma unroll 1
            for (int i = 0; i < 12; i++) {
                int n = i * 16 + w * 2;
                const float* kp0 = gK + ((size_t)b * NF_ + n) * H_;
                const float* kp1 = kp0 + H_;
                float s0 = 0.f, s1 = 0.f;
                #pragma unroll
                for (int j = 0; j < 8; j++) {
                    float4 q4  = *(const float4*)&SST[4 * lane + 128 * j];
                    float4 k0v = *(const float4*)(kp0 + 4 * lane + 128 * j);
                    float4 k1v = *(const float4*)(kp1 + 4 * lane + 128 * j);
                    s0 += q4.x*k0v.x + q4.y*k0v.y + q4.z*k0v.z + q4.w*k0v.w;
                    s1 += q4.x*k1v.x + q4.y*k1v.y + q4.z*k1v.z + q4.w*k1v.w;
                }
                #pragma unroll
                for (int o = 16; o; o >>= 1) {
                    s0 += __shfl_xor_sync(0xffffffffu, s0, o);
                    s1 += __shfl_xor_sync(0xffffffffu, s1, o);
                }
                if (lane == 0) { sScore[n] = s0 * 0.03125f; sScore[n+1] = s1 * 0.03125f; }
            }
            if (w < 2) {   // tail n = 192..195
                int n = 192 + w * 2;
                const float* kp0 = gK + ((size_t)b * NF_ + n) * H_;
                const float* kp1 = kp0 + H_;
                float s0 = 0.f, s1 = 0.f;
                #pragma unroll
                for (int j = 0; j < 8; j++) {
                    float4 q4  = *(const float4*)&SST[4 * lane + 128 * j];
                    float4 k0v = *(const float4*)(kp0 + 4 * lane + 128 * j);
                    float4 k1v = *(const float4*)(kp1 + 4 * lane + 128 * j);
                    s0 += q4.x*k0v.x + q4.y*k0v.y + q4.z*k0v.z + q4.w*k0v.w;
                    s1 += q4.x*k1v.x + q4.y*k1v.y + q4.z*k1v.z + q4.w*k1v.w;
                }
                #pragma unroll
                for (int o = 16; o; o >>= 1) {
                    s0 += __shfl_xor_sync(0xffffffffu, s0, o);
                    s1 += __shfl_xor_sync(0xffffffffu, s1, o);
                }
                if (lane == 0) { sScore[n] = s0 * 0.03125f; sScore[n+1] = s1 * 0.03125f; }
            }
            __syncthreads();
            // softmax over 196
            float v = (tid < NF_) ? sScore[tid] : -FLT_MAX;
            float m = v;
            #pragma unroll
            for (int o = 16; o; o >>= 1) m = fmaxf(m, __shfl_xor_sync(0xffffffffu, m, o));
            if (lane == 0) sred[w] = m;
            __syncthreads();
            if (tid == 0) {
                float mm = sred[0];
                #pragma unroll
                for (int i = 1; i < 8; i++) mm = fmaxf(mm, sred[i]);
                sbc = mm;
            }
            __syncthreads();
            float e = (tid < NF_) ? expf(v - sbc) : 0.f;
            float s2 = e;
            #pragma unroll
            for (int o = 16; o; o >>= 1) s2 += __shfl_xor_sync(0xffffffffu, s2, o);
            if (lane == 0) sred[w] = s2;
            __syncthreads();
            if (tid == 0) {
                float ss = 0.f;
                #pragma unroll
                for (int i = 0; i < 8; i++) ss += sred[i];
                sbc = ss;
            }
            __syncthreads();
            float p = e / sbc;
            if (tid < NF_) {
                sProb[tid] = p;
                attnb[((size_t)b * S_ + t) * NF_ + tid] = p;
            }
            __syncthreads();
            // ctx = attn @ V, unroll 8 (MLP=8)
            {
                const float* vb = gV + (size_t)b * NF_ * H_ + tid * 4;
                float4 a = make_float4(0.f, 0.f, 0.f, 0.f);
                #pragma unroll 1
                for (int n0b = 0; n0b < 192; n0b += 8) {
                    float4 vv[8];
                    #pragma unroll
                    for (int j = 0; j < 8; j++)
                        vv[j] = *(const float4*)(vb + (size_t)(n0b + j) * H_);
                    #pragma unroll
                    for (int j = 0; j < 8; j++) {
                        float pp = sProb[n0b + j];
                        a.x += pp * vv[j].x; a.y += pp * vv[j].y;
                        a.z += pp * vv[j].z; a.w += pp * vv[j].w;
                    }
                }
                #pragma unroll
                for (int j = 0; j < 4; j++) {
                    float4 v4 = *(const float4*)(vb + (size_t)(192 + j) * H_);
                    float pp = sProb[192 + j];
                    a.x += pp * v4.x; a.y += pp * v4.y;
                    a.z += pp * v4.z; a.w += pp * v4.w;
                }
                *(float4*)(gCtx + (size_t)b * H_ + tid * 4) = a;
            }
        }
        grid_bar();

        // ---- P3: x = h + ctx @ out_w^T + out_b  (stored to gO) ----
        gemv8(gCtx, SOW, SST, out_b, bx * 8, gH, gO, tid);
        grid_bar();

        // ---- P5: LN (merged) + gates + LSTM ----
        {
            // LN pre-pass: mu/rs for all 32 b from x = gO
            {
                int b = tid >> 3, sl = tid & 7;
                const float* xb = gO + (size_t)b * H_ + sl * 4;
                float s = 0.f, s2 = 0.f;
                #pragma unroll 8
                for (int i = 0; i < 32; i++) {
                    float4 v = *(const float4*)(xb + i * 32);
                    s  += v.x + v.y + v.z + v.w;
                    s2 += v.x*v.x + v.y*v.y + v.z*v.z + v.w*v.w;
                }
                #pragma unroll
                for (int o2 = 1; o2 < 8; o2 <<= 1) {
                    s  += __shfl_xor_sync(0xffffffffu, s,  o2);
                    s2 += __shfl_xor_sync(0xffffffffu, s2, o2);
                }
                if (sl == 0) {
                    float mu = s * (1.0f / H_);
                    float var = s2 * (1.0f / H_) - mu * mu;
                    sMu[b] = mu;
                    sRs[b] = rsqrtf(var + 1e-5f);
                }
            }
            __syncthreads();

            // two gate-pair sweeps
            #pragma unroll 1
            for (int gp = 0; gp < 4; gp += 2) {
                const float* W0 = SWH + (size_t)gp * 8192;
                const float* W1 = SWH + (size_t)(gp + 1) * 8192;
                unsigned long long aA[32], aB[32];
                #pragma unroll
                for (int p = 0; p < 32; p++) { aA[p] = 0ull; aB[p] = 0ull; }

                #pragma unroll 1
                for (int k0 = 0; k0 < H_; k0 += 128) {
                    __syncthreads();
                    {
                        int sb = tid >> 3, sl = tid & 7;
                        float mu = sMu[sb], rs = sRs[sb];
                        const float* src = gO + (size_t)sb * H_ + k0 + sl * 4;
                        const float* gg  = ln_g  + k0 + sl * 4;
                        const float* bb  = ln_b2 + k0 + sl * 4;
                        float* dst = SST + sb * 132 + sl * 4;
                        #pragma unroll
                        for (int i = 0; i < 4; i++) {
                            float4 x  = *(const float4*)(src + i * 32);
                            float4 gv = *(const float4*)(gg + i * 32);
                            float4 bv = *(const float4*)(bb + i * 32);
                            float4 r;
                            r.x = (x.x - mu) * rs * gv.x + bv.x;
                            r.y = (x.y - mu) * rs * gv.y + bv.y;
                            r.z = (x.z - mu) * rs * gv.z + bv.z;
                            r.w = (x.w - mu) * rs * gv.w + bv.w;
                            *(float4*)(dst + i * 32) = r;
                        }
                    }
                    __syncthreads();
                    ulonglong2 xp[4];
                    #pragma unroll
                    for (int b = 0; b < 4; b++)
                        xp[b] = *(const ulonglong2*)&SST[(4 * w + b) * 132 + 4 * lane];
                    #pragma unroll
                    for (int n = 0; n < 8; n++) {
                        ulonglong2 w0 = *(const ulonglong2*)&W0[n * H_ + k0 + 4 * lane];
                        ulonglong2 w1 = *(const ulonglong2*)&W1[n * H_ + k0 + 4 * lane];
                        #pragma unroll
                        for (int b = 0; b < 4; b++) {
                            fma2(aA[b * 8 + n], xp[b].x, w0.x);
                            fma2(aA[b * 8 + n], xp[b].y, w0.y);
                            fma2(aB[b * 8 + n], xp[b].x, w1.x);
                            fma2(aB[b * 8 + n], xp[b].y, w1.y);
                        }
                    }
                }
                float oA = 0.f, oB = 0.f;
                #pragma unroll
                for (int p = 0; p < 32; p++) {
                    float2 va = unpk2(aA[p]);
                    float2 vb = unpk2(aB[p]);
                    float sa = va.x + va.y, sb2 = vb.x + vb.y;
                    #pragma unroll
                    for (int o = 16; o; o >>= 1) {
                        sa  += __shfl_xor_sync(0xffffffffu, sa,  o);
                        sb2 += __shfl_xor_sync(0xffffffffu, sb2, o);
                    }
                    if (lane == p) { oA = sa; oB = sb2; }
                }
                int bg = 4 * w + (lane >> 3);
                int c  = lane & 7;
                int nA = gp * H_ + bx * 8 + c;
                int nB = (gp + 1) * H_ + bx * 8 + c;
                size_t xrow = ((size_t)bg * S_ + t) * (4 * H_);
                oA += b_hh[nA] + gXp[xrow + nA];
                oB += b_hh[nB] + gXp[xrow + nB];
                sG[gp * 256 + c * 32 + bg]       = oA;
                sG[(gp + 1) * 256 + c * 32 + bg] = oB;
            }
            __syncthreads();
            // LSTM pointwise
            int b = tid & 31, jj = tid >> 5;
            int j2 = bx * 8 + jj;
            float ii = sG[0 * 256 + jj * 32 + b];
            float ff = sG[1 * 256 + jj * 32 + b];
            float gg = sG[2 * 256 + jj * 32 + b];
            float oo = sG[3 * 256 + jj * 32 + b];
            float si = 1.f / (1.f + expf(-ii));
            float sf = 1.f / (1.f + expf(-ff));
            float so = 1.f / (1.f + expf(-oo));
            float cn = sf * gC[b * H_ + j2] + si * tanhf(gg);
            float hn = so * tanhf(cn);
            gC[b * H_ + j2] = cn;
            gH[b * H_ + j2] = hn;
            gHall[((size_t)b * S_ + t) * H_ + j2] = hn;
        }
        grid_bar();
    }
}

// ---------------- orchestration ----------------------------------------------
extern "C" void kernel_launch(void* const* d_in, const int* in_sizes, int n_in,
                              void* d_out, int out_size)
{
    const float* features = (const float*)d_in[0];
    const int*   captions = (const int*)  d_in[1];
    const float* emb      = (const float*)d_in[2];
    const float* q_w      = (const float*)d_in[3];
    const float* k_w      = (const float*)d_in[4];
    const float* v_w      = (const float*)d_in[5];
    const float* in_b     = (const float*)d_in[6];
    const float* out_w    = (const float*)d_in[7];
    const float* out_b    = (const float*)d_in[8];
    const float* h0_w     = (const float*)d_in[9];
    const float* h0_b     = (const float*)d_in[10];
    const float* c0_w     = (const float*)d_in[11];
    const float* c0_b     = (const float*)d_in[12];
    const float* w_ih     = (const float*)d_in[13];
    const float* b_ih     = (const float*)d_in[14];
    const float* w_hh     = (const float*)d_in[15];
    const float* b_hh     = (const float*)d_in[16];
    const float* ln_g     = (const float*)d_in[17];
    const float* ln_b2    = (const float*)d_in[18];
    const float* lin_w    = (const float*)d_in[19];
    const float* lin_b    = (const float*)d_in[20];

    float* sc = nullptr;
    cudaGetSymbolAddress((void**)&sc, g_scratch);
    float* gK    = sc + OFF_K;
    float* gV    = sc + OFF_V;
    float* gMean = sc + OFF_MEAN;
    float* gH    = sc + OFF_H;
    float* gC    = sc + OFF_C;
    float* gQ    = sc + OFF_Q;
    float* gCtx  = sc + OFF_CTX;
    float* gO    = sc + OFF_O;
    float* gEmb  = sc + OFF_EMB;
    float* gXp   = sc + OFF_XP;
    float* gHall = sc + OFF_HALL;
    float* gAd   = sc + OFF_AD;

    float* out   = (float*)d_out;
    float* preds = out;
    const size_t PRED = (size_t)B_ * S_ * V_;
    bool wa = ((size_t)out_size >= PRED + (size_t)B_ * S_ * NF_);
    float* attnb = wa ? (out + PRED) : gAd;

    const int REC_SMEM = 53376 * 4;   // SQW+SOW+SWH+SST(32x132)
    cudaFuncSetAttribute(recurrence_kernel,
                         cudaFuncAttributeMaxDynamicSharedMemorySize, REC_SMEM);

    // ---- setup (hoisted) ----
    mean_gelu_kernel<<<dim3(ENC_ / 256, B_), 256>>>(features, gMean);
    gemvM32<<<H_ / 8, 256>>>(gMean, h0_w, h0_b, gH, H_, ENC_);
    gemvM32<<<H_ / 8, 256>>>(gMean, c0_w, c0_b, gC, H_, ENC_);
    gemm128<<<dim3(H_ / 128, (B_ * NF_) / 128), 256>>>(
        features, ENC_, k_w, in_b + H_,     gK, H_, ENC_);
    gemm128<<<dim3(H_ / 128, (B_ * NF_) / 128), 256>>>(
        features, ENC_, v_w, in_b + 2 * H_, gV, H_, ENC_);
    gather_kernel<<<(B_ * S_ * ED_) / 256, 256>>>(emb, captions, gEmb);
    gemm128<<<dim3((4 * H_) / 128, (B_ * S_) / 128), 256>>>(
        gEmb, ED_, w_ih, b_ih, gXp, 4 * H_, ED_);

    // ---- recurrence in one persistent kernel ----
    recurrence_kernel<<<NB_, 256, REC_SMEM>>>(
        q_w, in_b, out_w, out_b, w_hh, b_hh, ln_g, ln_b2,
        gK, gV, gXp, gH, gC, gQ, gCtx, gO, gHall, attnb);

    // ---- batched logits ----
    gemm128<<<dim3(V_ / 128, (B_ * S_) / 128), 256>>>(
        gHall, H_, lin_w, lin_b, preds, V_, H_);
}

// round 7
// speedup vs baseline: 1.5318x; 1.5318x over previous
#include <cuda_runtime.h>
#include <math.h>
#include <float.h>

#define B_   32
#define NF_  196
#define ENC_ 2048
#define V_   32000
#define ED_  512
#define S_   32
#define H_   1024
#define NB_  128        // persistent grid size (all co-resident on 148 SMs)

// ---------------- f32x2 packed helpers (sm_103a) -----------------------------
__device__ __forceinline__ void fma2(unsigned long long& d,
                                     unsigned long long a, unsigned long long b) {
    asm("fma.rn.f32x2 %0, %1, %2, %0;" : "+l"(d) : "l"(a), "l"(b));
}
__device__ __forceinline__ unsigned long long pack2(float lo, float hi) {
    unsigned long long r;
    asm("mov.b64 %0, {%1, %2};" : "=l"(r) : "f"(lo), "f"(hi));
    return r;
}
__device__ __forceinline__ float2 unpk2(unsigned long long v) {
    float2 r;
    asm("mov.b64 {%0, %1}, %2;" : "=f"(r.x), "=f"(r.y) : "l"(v));
    return r;
}

// ---------------- scratch ----------------------------------------------------
static constexpr size_t SZ_K    = (size_t)B_ * NF_ * H_;
static constexpr size_t OFF_K   = 0;
static constexpr size_t OFF_V   = OFF_K + SZ_K;
static constexpr size_t OFF_MEAN= OFF_V + SZ_K;
static constexpr size_t OFF_H   = OFF_MEAN + (size_t)B_ * ENC_;
static constexpr size_t OFF_C   = OFF_H   + (size_t)B_ * H_;
static constexpr size_t OFF_Q   = OFF_C   + (size_t)B_ * H_;
static constexpr size_t OFF_CTX = OFF_Q   + (size_t)B_ * H_;
static constexpr size_t OFF_O   = OFF_CTX + (size_t)B_ * H_;
static constexpr size_t OFF_EMB = OFF_O   + (size_t)B_ * H_;
static constexpr size_t OFF_XP  = OFF_EMB + (size_t)B_ * S_ * ED_;
static constexpr size_t OFF_HALL= OFF_XP  + (size_t)B_ * S_ * 4 * H_;
static constexpr size_t OFF_AD  = OFF_HALL+ (size_t)B_ * S_ * H_;
static constexpr size_t TOTAL_F = OFF_AD  + (size_t)B_ * S_ * NF_;

__device__ float g_scratch[TOTAL_F];
__device__ unsigned g_bar_count = 0;
__device__ unsigned g_bar_gen   = 0;

// ---------------- grid-wide barrier ------------------------------------------
__device__ __forceinline__ void grid_bar() {
    __syncthreads();
    if (threadIdx.x == 0) {
        __threadfence();
        unsigned gen = *(volatile unsigned*)&g_bar_gen;
        unsigned a = atomicAdd(&g_bar_count, 1u);
        if (a == NB_ - 1) {
            atomicExch(&g_bar_count, 0u);
            __threadfence();
            atomicAdd(&g_bar_gen, 1u);
        } else {
            while (*(volatile unsigned*)&g_bar_gen == gen) __nanosleep(64);
        }
        __threadfence();
    }
    __syncthreads();
}

// ---------------- mean over N + exact gelu -----------------------------------
__global__ __launch_bounds__(256) void mean_gelu_kernel(
    const float* __restrict__ feat, float* __restrict__ outMean)
{
    int b = blockIdx.y;
    int e = blockIdx.x * 256 + threadIdx.x;
    const float* p = feat + (size_t)b * NF_ * ENC_ + e;
    float s = 0.f;
    #pragma unroll 4
    for (int n = 0; n < NF_; n++) s += p[(size_t)n * ENC_];
    s *= (1.0f / (float)NF_);
    outMean[(size_t)b * ENC_ + e] = 0.5f * s * (1.0f + erff(s * 0.70710678118654752f));
}

// ---------------- embedding gather -------------------------------------------
__global__ __launch_bounds__(256) void gather_kernel(
    const float* __restrict__ emb, const int* __restrict__ cap,
    float* __restrict__ out)
{
    int idx = blockIdx.x * 256 + threadIdx.x;
    int d  = idx & (ED_ - 1);
    int bs = idx >> 9;
    out[idx] = emb[(size_t)cap[bs] * ED_ + d];
}

// ---------------- batched GEMV for M=32 (setup h0/c0 only) -------------------
__global__ __launch_bounds__(256) void gemvM32(
    const float* __restrict__ A, const float* __restrict__ W,
    const float* __restrict__ bias, float* __restrict__ C, int ldc, int K)
{
    __shared__ float sA[32][64];
    int tid = threadIdx.x, lane = tid & 31, w = tid >> 5;
    int n = blockIdx.x * 8 + w;
    const float* Wn = W + (size_t)n * K;
    float acc[32];
    #pragma unroll
    for (int b = 0; b < 32; b++) acc[b] = 0.f;
    for (int k0 = 0; k0 < K; k0 += 64) {
        __syncthreads();
        int kk = tid & 63, bb = tid >> 6;
        #pragma unroll
        for (int i = 0; i < 8; i++)
            sA[bb + i * 4][kk] = A[(size_t)(bb + i * 4) * K + k0 + kk];
        __syncthreads();
        float w0 = Wn[k0 + lane], w1 = Wn[k0 + 32 + lane];
        #pragma unroll
        for (int b = 0; b < 32; b++)
            acc[b] += w0 * sA[b][lane] + w1 * sA[b][lane + 32];
    }
    float out = 0.f;
    #pragma unroll
    for (int b = 0; b < 32; b++) {
        float v = acc[b];
        #pragma unroll
        for (int o = 16; o; o >>= 1) v += __shfl_xor_sync(0xffffffffu, v, o);
        if (lane == b) out = v;
    }
    C[(size_t)lane * (size_t)ldc + n] = out + bias[n];
}

// ---------------- 128x128 SGEMM, single-buffer, f32x2 (round-4 proven) -------
__global__ __launch_bounds__(256, 2) void gemm128(
    const float* __restrict__ A, int lda,
    const float* __restrict__ W,          // [N,K]
    const float* __restrict__ bias,
    float* __restrict__ C, int ldc, int K)
{
    __shared__ float sA[16][132];
    __shared__ float sB[16][132];
    int tid = threadIdx.x;
    int m0 = blockIdx.y * 128, n0 = blockIdx.x * 128;
    int lr = tid >> 2;
    int lk = (tid & 3) * 4;
    const float* Ab = A + (size_t)m0 * lda + lk;
    const float* Wb = W + (size_t)n0 * K + lk;
    int tx = tid & 15, ty = tid >> 4;

    unsigned long long acc2[8][4];
    #pragma unroll
    for (int i = 0; i < 8; i++)
        #pragma unroll
        for (int j = 0; j < 4; j++) acc2[i][j] = 0ull;

    for (int k0 = 0; k0 < K; k0 += 16) {
        float4 a0 = *(const float4*)(Ab + (size_t)lr * lda + k0);
        float4 a1 = *(const float4*)(Ab + (size_t)(lr + 64) * lda + k0);
        float4 b0 = *(const float4*)(Wb + (size_t)lr * K + k0);
        float4 b1 = *(const float4*)(Wb + (size_t)(lr + 64) * K + k0);
        __syncthreads();
        sA[lk+0][lr]=a0.x; sA[lk+1][lr]=a0.y; sA[lk+2][lr]=a0.z; sA[lk+3][lr]=a0.w;
        sA[lk+0][lr+64]=a1.x; sA[lk+1][lr+64]=a1.y; sA[lk+2][lr+64]=a1.z; sA[lk+3][lr+64]=a1.w;
        sB[lk+0][lr]=b0.x; sB[lk+1][lr]=b0.y; sB[lk+2][lr]=b0.z; sB[lk+3][lr]=b0.w;
        sB[lk+0][lr+64]=b1.x; sB[lk+1][lr+64]=b1.y; sB[lk+2][lr+64]=b1.z; sB[lk+3][lr+64]=b1.w;
        __syncthreads();
        #pragma unroll
        for (int k = 0; k < 16; k++) {
            float ar[8];
            *(float4*)&ar[0] = *(const float4*)&sA[k][ty * 8];
            *(float4*)&ar[4] = *(const float4*)&sA[k][ty * 8 + 4];
            const unsigned long long* pb =
                (const unsigned long long*)&sB[k][tx * 8];
            unsigned long long bb0 = pb[0], bb1 = pb[1], bb2 = pb[2], bb3 = pb[3];
            #pragma unroll
            for (int i = 0; i < 8; i++) {
                unsigned long long aa = pack2(ar[i], ar[i]);
                fma2(acc2[i][0], aa, bb0);
                fma2(acc2[i][1], aa, bb1);
                fma2(acc2[i][2], aa, bb2);
                fma2(acc2[i][3], aa, bb3);
            }
        }
    }

    int n = n0 + tx * 8;
    float bb[8] = {0.f,0.f,0.f,0.f,0.f,0.f,0.f,0.f};
    if (bias) {
        *(float4*)&bb[0] = *(const float4*)(bias + n);
        *(float4*)&bb[4] = *(const float4*)(bias + n + 4);
    }
    #pragma unroll
    for (int i = 0; i < 8; i++) {
        size_t m = (size_t)(m0 + ty * 8 + i);
        float2 v0 = unpk2(acc2[i][0]);
        float2 v1 = unpk2(acc2[i][1]);
        float2 v2 = unpk2(acc2[i][2]);
        float2 v3 = unpk2(acc2[i][3]);
        float4 r0 = make_float4(v0.x+bb[0], v0.y+bb[1], v1.x+bb[2], v1.y+bb[3]);
        float4 r1 = make_float4(v2.x+bb[4], v2.y+bb[5], v3.x+bb[6], v3.y+bb[7]);
        *(float4*)(C + m * (size_t)ldc + n)     = r0;
        *(float4*)(C + m * (size_t)ldc + n + 4) = r1;
    }
}

// ---------------- persistent recurrence kernel -------------------------------
// Dynamic smem (floats): SQW[8192] SOW[8192] SWH[32768] SLNG[1024] SLNB[1024]
extern __shared__ float dsm[];

// warp computes 4 batches x 8 cols; x read DIRECTLY from global (no smem/syncs)
__device__ __forceinline__ void gemv_direct(
    const float* __restrict__ Ag,      // [32,1024] global x
    const float* sW,                   // 8 cols x 1024, row-major in smem
    const float* __restrict__ bias, int n0,
    const float* __restrict__ addH,    // optional: out += addH[b][n]
    float* __restrict__ Cg, int tid)
{
    int lane = tid & 31, w = tid >> 5;
    unsigned long long acc[32];        // [b_local*8 + n]
    #pragma unroll
    for (int p = 0; p < 32; p++) acc[p] = 0ull;

    const float* xb = Ag + (size_t)(4 * w) * H_ + 4 * lane;
    #pragma unroll
    for (int c = 0; c < 8; c++) {
        ulonglong2 xv[4];
        #pragma unroll
        for (int b = 0; b < 4; b++)
            xv[b] = *(const ulonglong2*)(xb + (size_t)b * H_ + c * 128);
        #pragma unroll
        for (int n = 0; n < 8; n++) {
            ulonglong2 wv = *(const ulonglong2*)&sW[n * H_ + c * 128 + 4 * lane];
            #pragma unroll
            for (int b = 0; b < 4; b++) {
                fma2(acc[b * 8 + n], xv[b].x, wv.x);
                fma2(acc[b * 8 + n], xv[b].y, wv.y);
            }
        }
    }
    float outv = 0.f;
    #pragma unroll
    for (int p = 0; p < 32; p++) {
        float2 v = unpk2(acc[p]);
        float s = v.x + v.y;
        #pragma unroll
        for (int o = 16; o; o >>= 1) s += __shfl_xor_sync(0xffffffffu, s, o);
        if (lane == p) outv = s;
    }
    int bg = 4 * w + (lane >> 3);
    int ng = n0 + (lane & 7);
    float r = outv + bias[ng];
    if (addH) r += addH[(size_t)bg * H_ + ng];
    Cg[(size_t)bg * H_ + ng] = r;
}

__global__ __launch_bounds__(256, 1) void recurrence_kernel(
    const float* __restrict__ q_w,  const float* __restrict__ in_b,
    const float* __restrict__ out_w,const float* __restrict__ out_b,
    const float* __restrict__ w_hh, const float* __restrict__ b_hh,
    const float* __restrict__ ln_g, const float* __restrict__ ln_b2,
    const float* __restrict__ gK,   const float* __restrict__ gV,
    const float* __restrict__ gXp,
    float* gH, float* gC, float* gQ,
    float* gCtx, float* gO, float* gHall, float* attnb)
{
    __shared__ float sQ[1024];
    __shared__ float sScore[224];
    __shared__ float sProb[224];
    __shared__ float sred[8];
    __shared__ float sbc;
    __shared__ float sG[1024];
    __shared__ float sMu[32], sRs[32];

    float* SQW  = dsm;
    float* SOW  = dsm + 8192;
    float* SWH  = dsm + 16384;
    float* SLNG = dsm + 49152;
    float* SLNB = dsm + 50176;

    int tid = threadIdx.x, lane = tid & 31, w = tid >> 5;
    int bx = blockIdx.x;

    // ---- one-time preload: weight slices + LN params ----
    for (int i = tid; i < 8192; i += 256) {
        SQW[i] = q_w [(size_t)bx * 8192 + i];
        SOW[i] = out_w[(size_t)bx * 8192 + i];
    }
    for (int g = 0; g < 4; g++)
        for (int i = tid; i < 8192; i += 256)
            SWH[g * 8192 + i] = w_hh[((size_t)g * H_ + bx * 8) * H_ + i];
    for (int i = tid; i < 1024; i += 256) {
        SLNG[i] = ln_g[i];
        SLNB[i] = ln_b2[i];
    }
    __syncthreads();

    for (int t = 0; t < S_; t++) {
        // ---- P0: q = h @ q_w^T + in_b[:H] ----
        gemv_direct(gH, SQW, in_b, bx * 8, nullptr, gQ, tid);
        grid_bar();

        // ---- P1: fused scores + softmax + ctx (blocks 0..31) ----
        if (bx < 32) {
            int b = bx;
            for (int i = tid; i < 1024; i += 256)
                sQ[i] = gQ[(size_t)b * H_ + i];
            __syncthreads();
            // scores: 2 per warp per iteration (MLP=16); 196 = 12*16 + 4
            #pragma unroll 1
            for (int i = 0; i < 12; i++) {
                int n = i * 16 + w * 2;
                const float* kp0 = gK + ((size_t)b * NF_ + n) * H_;
                const float* kp1 = kp0 + H_;
                float s0 = 0.f, s1 = 0.f;
                #pragma unroll
                for (int j = 0; j < 8; j++) {
                    float4 q4  = *(const float4*)&sQ[4 * lane + 128 * j];
                    float4 k0v = *(const float4*)(kp0 + 4 * lane + 128 * j);
                    float4 k1v = *(const float4*)(kp1 + 4 * lane + 128 * j);
                    s0 += q4.x*k0v.x + q4.y*k0v.y + q4.z*k0v.z + q4.w*k0v.w;
                    s1 += q4.x*k1v.x + q4.y*k1v.y + q4.z*k1v.z + q4.w*k1v.w;
                }
                #pragma unroll
                for (int o = 16; o; o >>= 1) {
                    s0 += __shfl_xor_sync(0xffffffffu, s0, o);
                    s1 += __shfl_xor_sync(0xffffffffu, s1, o);
                }
                if (lane == 0) { sScore[n] = s0 * 0.03125f; sScore[n+1] = s1 * 0.03125f; }
            }
            if (w < 2) {   // tail n = 192..195
                int n = 192 + w * 2;
                const float* kp0 = gK + ((size_t)b * NF_ + n) * H_;
                const float* kp1 = kp0 + H_;
                float s0 = 0.f, s1 = 0.f;
                #pragma unroll
                for (int j = 0; j < 8; j++) {
                    float4 q4  = *(const float4*)&sQ[4 * lane + 128 * j];
                    float4 k0v = *(const float4*)(kp0 + 4 * lane + 128 * j);
                    float4 k1v = *(const float4*)(kp1 + 4 * lane + 128 * j);
                    s0 += q4.x*k0v.x + q4.y*k0v.y + q4.z*k0v.z + q4.w*k0v.w;
                    s1 += q4.x*k1v.x + q4.y*k1v.y + q4.z*k1v.z + q4.w*k1v.w;
                }
                #pragma unroll
                for (int o = 16; o; o >>= 1) {
                    s0 += __shfl_xor_sync(0xffffffffu, s0, o);
                    s1 += __shfl_xor_sync(0xffffffffu, s1, o);
                }
                if (lane == 0) { sScore[n] = s0 * 0.03125f; sScore[n+1] = s1 * 0.03125f; }
            }
            __syncthreads();
            // softmax over 196
            float v = (tid < NF_) ? sScore[tid] : -FLT_MAX;
            float m = v;
            #pragma unroll
            for (int o = 16; o; o >>= 1) m = fmaxf(m, __shfl_xor_sync(0xffffffffu, m, o));
            if (lane == 0) sred[w] = m;
            __syncthreads();
            if (tid == 0) {
                float mm = sred[0];
                #pragma unroll
                for (int i = 1; i < 8; i++) mm = fmaxf(mm, sred[i]);
                sbc = mm;
            }
            __syncthreads();
            float e = (tid < NF_) ? expf(v - sbc) : 0.f;
            float s2 = e;
            #pragma unroll
            for (int o = 16; o; o >>= 1) s2 += __shfl_xor_sync(0xffffffffu, s2, o);
            if (lane == 0) sred[w] = s2;
            __syncthreads();
            if (tid == 0) {
                float ss = 0.f;
                #pragma unroll
                for (int i = 0; i < 8; i++) ss += sred[i];
                sbc = ss;
            }
            __syncthreads();
            float p = e / sbc;
            if (tid < NF_) {
                sProb[tid] = p;
                attnb[((size_t)b * S_ + t) * NF_ + tid] = p;
            }
            __syncthreads();
            // ctx = attn @ V, unroll 8
            {
                const float* vb = gV + (size_t)b * NF_ * H_ + tid * 4;
                float4 a = make_float4(0.f, 0.f, 0.f, 0.f);
                #pragma unroll 1
                for (int n0b = 0; n0b < 192; n0b += 8) {
                    float4 vv[8];
                    #pragma unroll
                    for (int j = 0; j < 8; j++)
                        vv[j] = *(const float4*)(vb + (size_t)(n0b + j) * H_);
                    #pragma unroll
                    for (int j = 0; j < 8; j++) {
                        float pp = sProb[n0b + j];
                        a.x += pp * vv[j].x; a.y += pp * vv[j].y;
                        a.z += pp * vv[j].z; a.w += pp * vv[j].w;
                    }
                }
                #pragma unroll
                for (int j = 0; j < 4; j++) {
                    float4 v4 = *(const float4*)(vb + (size_t)(192 + j) * H_);
                    float pp = sProb[192 + j];
                    a.x += pp * v4.x; a.y += pp * v4.y;
                    a.z += pp * v4.z; a.w += pp * v4.w;
                }
                *(float4*)(gCtx + (size_t)b * H_ + tid * 4) = a;
            }
        }
        grid_bar();

        // ---- P3: x = h + ctx @ out_w^T + out_b  (stored to gO) ----
        gemv_direct(gCtx, SOW, out_b, bx * 8, gH, gO, tid);
        grid_bar();

        // ---- P5: LN (on the fly) + gates + LSTM ----
        {
            // LN pre-pass: mu/rs for all 32 b from x = gO
            {
                int b = tid >> 3, sl = tid & 7;
                const float* xb = gO + (size_t)b * H_ + sl * 4;
                float s = 0.f, s2 = 0.f;
                #pragma unroll 8
                for (int i = 0; i < 32; i++) {
                    float4 v = *(const float4*)(xb + i * 32);
                    s  += v.x + v.y + v.z + v.w;
                    s2 += v.x*v.x + v.y*v.y + v.z*v.z + v.w*v.w;
                }
                #pragma unroll
                for (int o2 = 1; o2 < 8; o2 <<= 1) {
                    s  += __shfl_xor_sync(0xffffffffu, s,  o2);
                    s2 += __shfl_xor_sync(0xffffffffu, s2, o2);
                }
                if (sl == 0) {
                    float mu = s * (1.0f / H_);
                    float var = s2 * (1.0f / H_) - mu * mu;
                    sMu[b] = mu;
                    sRs[b] = rsqrtf(var + 1e-5f);
                }
            }
            __syncthreads();

            const float* xb = gO + (size_t)(4 * w) * H_ + 4 * lane;
            float muv[4], rsv[4];
            #pragma unroll
            for (int b = 0; b < 4; b++) {
                muv[b] = sMu[4 * w + b];
                rsv[b] = sRs[4 * w + b];
            }

            // two gate-pair sweeps, x LayerNorm'd on the fly (no smem staging)
            #pragma unroll 1
            for (int p2 = 0; p2 < 2; p2++) {
                int g0 = 2 * p2, g1 = 2 * p2 + 1;
                const float* W0 = SWH + (size_t)g0 * 8192;
                const float* W1 = SWH + (size_t)g1 * 8192;
                unsigned long long aA[32], aB[32];
                #pragma unroll
                for (int p = 0; p < 32; p++) { aA[p] = 0ull; aB[p] = 0ull; }

                #pragma unroll
                for (int c = 0; c < 8; c++) {
                    float4 g4 = *(const float4*)&SLNG[c * 128 + 4 * lane];
                    float4 b4 = *(const float4*)&SLNB[c * 128 + 4 * lane];
                    ulonglong2 xn[4];
                    #pragma unroll
                    for (int b = 0; b < 4; b++) {
                        float4 x = *(const float4*)(xb + (size_t)b * H_ + c * 128);
                        float mu = muv[b], rs = rsv[b];
                        float4 r;
                        r.x = (x.x - mu) * rs * g4.x + b4.x;
                        r.y = (x.y - mu) * rs * g4.y + b4.y;
                        r.z = (x.z - mu) * rs * g4.z + b4.z;
                        r.w = (x.w - mu) * rs * g4.w + b4.w;
                        xn[b].x = pack2(r.x, r.y);
                        xn[b].y = pack2(r.z, r.w);
                    }
                    #pragma unroll
                    for (int n = 0; n < 8; n++) {
                        ulonglong2 w0 = *(const ulonglong2*)&W0[n * H_ + c * 128 + 4 * lane];
                        ulonglong2 w1 = *(const ulonglong2*)&W1[n * H_ + c * 128 + 4 * lane];
                        #pragma unroll
                        for (int b = 0; b < 4; b++) {
                            fma2(aA[b * 8 + n], xn[b].x, w0.x);
                            fma2(aA[b * 8 + n], xn[b].y, w0.y);
                            fma2(aB[b * 8 + n], xn[b].x, w1.x);
                            fma2(aB[b * 8 + n], xn[b].y, w1.y);
                        }
                    }
                }
                float oA = 0.f, oB = 0.f;
                #pragma unroll
                for (int p = 0; p < 32; p++) {
                    float2 va = unpk2(aA[p]);
                    float2 vb = unpk2(aB[p]);
                    float sa = va.x + va.y, sb2 = vb.x + vb.y;
                    #pragma unroll
                    for (int o = 16; o; o >>= 1) {
                        sa  += __shfl_xor_sync(0xffffffffu, sa,  o);
                        sb2 += __shfl_xor_sync(0xffffffffu, sb2, o);
                    }
                    if (lane == p) { oA = sa; oB = sb2; }
                }
                int bg = 4 * w + (lane >> 3);
                int c  = lane & 7;
                int nA = g0 * H_ + bx * 8 + c;
                int nB = g1 * H_ + bx * 8 + c;
                size_t xrow = ((size_t)bg * S_ + t) * (4 * H_);
                oA += b_hh[nA] + gXp[xrow + nA];
                oB += b_hh[nB] + gXp[xrow + nB];
                sG[g0 * 256 + c * 32 + bg] = oA;
                sG[g1 * 256 + c * 32 + bg] = oB;
            }
            __syncthreads();
            // LSTM pointwise
            int b = tid & 31, jj = tid >> 5;
            int j2 = bx * 8 + jj;
            float ii = sG[0 * 256 + jj * 32 + b];
            float ff = sG[1 * 256 + jj * 32 + b];
            float gg = sG[2 * 256 + jj * 32 + b];
            float oo = sG[3 * 256 + jj * 32 + b];
            float si = 1.f / (1.f + expf(-ii));
            float sf = 1.f / (1.f + expf(-ff));
            float so = 1.f / (1.f + expf(-oo));
            float cn = sf * gC[b * H_ + j2] + si * tanhf(gg);
            float hn = so * tanhf(cn);
            gC[b * H_ + j2] = cn;
            gH[b * H_ + j2] = hn;
            gHall[((size_t)b * S_ + t) * H_ + j2] = hn;
        }
        grid_bar();
    }
}

// ---------------- orchestration ----------------------------------------------
extern "C" void kernel_launch(void* const* d_in, const int* in_sizes, int n_in,
                              void* d_out, int out_size)
{
    const float* features = (const float*)d_in[0];
    const int*   captions = (const int*)  d_in[1];
    const float* emb      = (const float*)d_in[2];
    const float* q_w      = (const float*)d_in[3];
    const float* k_w      = (const float*)d_in[4];
    const float* v_w      = (const float*)d_in[5];
    const float* in_b     = (const float*)d_in[6];
    const float* out_w    = (const float*)d_in[7];
    const float* out_b    = (const float*)d_in[8];
    const float* h0_w     = (const float*)d_in[9];
    const float* h0_b     = (const float*)d_in[10];
    const float* c0_w     = (const float*)d_in[11];
    const float* c0_b     = (const float*)d_in[12];
    const float* w_ih     = (const float*)d_in[13];
    const float* b_ih     = (const float*)d_in[14];
    const float* w_hh     = (const float*)d_in[15];
    const float* b_hh     = (const float*)d_in[16];
    const float* ln_g     = (const float*)d_in[17];
    const float* ln_b2    = (const float*)d_in[18];
    const float* lin_w    = (const float*)d_in[19];
    const float* lin_b    = (const float*)d_in[20];

    float* sc = nullptr;
    cudaGetSymbolAddress((void**)&sc, g_scratch);
    float* gK    = sc + OFF_K;
    float* gV    = sc + OFF_V;
    float* gMean = sc + OFF_MEAN;
    float* gH    = sc + OFF_H;
    float* gC    = sc + OFF_C;
    float* gQ    = sc + OFF_Q;
    float* gCtx  = sc + OFF_CTX;
    float* gO    = sc + OFF_O;
    float* gEmb  = sc + OFF_EMB;
    float* gXp   = sc + OFF_XP;
    float* gHall = sc + OFF_HALL;
    float* gAd   = sc + OFF_AD;

    float* out   = (float*)d_out;
    float* preds = out;
    const size_t PRED = (size_t)B_ * S_ * V_;
    bool wa = ((size_t)out_size >= PRED + (size_t)B_ * S_ * NF_);
    float* attnb = wa ? (out + PRED) : gAd;

    const int REC_SMEM = 51200 * 4;   // SQW+SOW+SWH+SLNG+SLNB = 200 KB
    cudaFuncSetAttribute(recurrence_kernel,
                         cudaFuncAttributeMaxDynamicSharedMemorySize, REC_SMEM);

    // ---- setup (hoisted) ----
    mean_gelu_kernel<<<dim3(ENC_ / 256, B_), 256>>>(features, gMean);
    gemvM32<<<H_ / 8, 256>>>(gMean, h0_w, h0_b, gH, H_, ENC_);
    gemvM32<<<H_ / 8, 256>>>(gMean, c0_w, c0_b, gC, H_, ENC_);
    gemm128<<<dim3(H_ / 128, (B_ * NF_) / 128), 256>>>(
        features, ENC_, k_w, in_b + H_,     gK, H_, ENC_);
    gemm128<<<dim3(H_ / 128, (B_ * NF_) / 128), 256>>>(
        features, ENC_, v_w, in_b + 2 * H_, gV, H_, ENC_);
    gather_kernel<<<(B_ * S_ * ED_) / 256, 256>>>(emb, captions, gEmb);
    gemm128<<<dim3((4 * H_) / 128, (B_ * S_) / 128), 256>>>(
        gEmb, ED_, w_ih, b_ih, gXp, 4 * H_, ED_);

    // ---- recurrence in one persistent kernel ----
    recurrence_kernel<<<NB_, 256, REC_SMEM>>>(
        q_w, in_b, out_w, out_b, w_hh, b_hh, ln_g, ln_b2,
        gK, gV, gXp, gH, gC, gQ, gCtx, gO, gHall, attnb);

    // ---- batched logits ----
    gemm128<<<dim3(V_ / 128, (B_ * S_) / 128), 256>>>(
        gHall, H_, lin_w, lin_b, preds, V_, H_);
}

// round 8
// speedup vs baseline: 1.6327x; 1.0659x over previous
#include <cuda_runtime.h>
#include <math.h>
#include <float.h>

#define B_   32
#define NF_  196
#define ENC_ 2048
#define V_   32000
#define ED_  512
#define S_   32
#define H_   1024
#define NB_  128        // persistent grid size (all co-resident on 148 SMs)

// ---------------- f32x2 packed helpers (sm_103a) -----------------------------
__device__ __forceinline__ void fma2(unsigned long long& d,
                                     unsigned long long a, unsigned long long b) {
    asm("fma.rn.f32x2 %0, %1, %2, %0;" : "+l"(d) : "l"(a), "l"(b));
}
__device__ __forceinline__ unsigned long long pack2(float lo, float hi) {
    unsigned long long r;
    asm("mov.b64 %0, {%1, %2};" : "=l"(r) : "f"(lo), "f"(hi));
    return r;
}
__device__ __forceinline__ float2 unpk2(unsigned long long v) {
    float2 r;
    asm("mov.b64 {%0, %1}, %2;" : "=f"(r.x), "=f"(r.y) : "l"(v));
    return r;
}
__device__ __forceinline__ unsigned su32(const void* p) {
    return (unsigned)__cvta_generic_to_shared(p);
}
#define CP16(dst, src) \
    asm volatile("cp.async.cg.shared.global [%0], [%1], 16;" :: "r"(dst), "l"(src))
#define CPCOMMIT() asm volatile("cp.async.commit_group;")
#define CPWAIT(n)  asm volatile("cp.async.wait_group %0;" :: "n"(n))

// ---------------- scratch ----------------------------------------------------
static constexpr size_t SZ_K    = (size_t)B_ * NF_ * H_;
static constexpr size_t OFF_K   = 0;
static constexpr size_t OFF_V   = OFF_K + SZ_K;
static constexpr size_t OFF_MEAN= OFF_V + SZ_K;
static constexpr size_t OFF_H   = OFF_MEAN + (size_t)B_ * ENC_;
static constexpr size_t OFF_C   = OFF_H   + (size_t)B_ * H_;
static constexpr size_t OFF_Q   = OFF_C   + (size_t)B_ * H_;
static constexpr size_t OFF_CTX = OFF_Q   + (size_t)B_ * H_;
static constexpr size_t OFF_O   = OFF_CTX + (size_t)B_ * H_;
static constexpr size_t OFF_EMB = OFF_O   + (size_t)B_ * H_;
static constexpr size_t OFF_XP  = OFF_EMB + (size_t)B_ * S_ * ED_;
static constexpr size_t OFF_HALL= OFF_XP  + (size_t)B_ * S_ * 4 * H_;
static constexpr size_t OFF_AD  = OFF_HALL+ (size_t)B_ * S_ * H_;
// transposed weights (K-major)
static constexpr size_t OFF_KT  = OFF_AD  + (size_t)B_ * S_ * NF_;
static constexpr size_t OFF_VT  = OFF_KT  + (size_t)ENC_ * H_;
static constexpr size_t OFF_WIT = OFF_VT  + (size_t)ENC_ * H_;
static constexpr size_t OFF_LWT = OFF_WIT + (size_t)ED_ * 4 * H_;
static constexpr size_t TOTAL_F = OFF_LWT + (size_t)H_ * V_;

__device__ float g_scratch[TOTAL_F];
__device__ unsigned g_bar_count = 0;
__device__ unsigned g_bar_gen   = 0;

// ---------------- grid-wide barrier ------------------------------------------
__device__ __forceinline__ void grid_bar() {
    __syncthreads();
    if (threadIdx.x == 0) {
        __threadfence();
        unsigned gen = *(volatile unsigned*)&g_bar_gen;
        unsigned a = atomicAdd(&g_bar_count, 1u);
        if (a == NB_ - 1) {
            atomicExch(&g_bar_count, 0u);
            __threadfence();
            atomicAdd(&g_bar_gen, 1u);
        } else {
            while (*(volatile unsigned*)&g_bar_gen == gen) __nanosleep(64);
        }
        __threadfence();
    }
    __syncthreads();
}

// ---------------- mean over N + exact gelu -----------------------------------
__global__ __launch_bounds__(256) void mean_gelu_kernel(
    const float* __restrict__ feat, float* __restrict__ outMean)
{
    int b = blockIdx.y;
    int e = blockIdx.x * 256 + threadIdx.x;
    const float* p = feat + (size_t)b * NF_ * ENC_ + e;
    float s = 0.f;
    #pragma unroll 4
    for (int n = 0; n < NF_; n++) s += p[(size_t)n * ENC_];
    s *= (1.0f / (float)NF_);
    outMean[(size_t)b * ENC_ + e] = 0.5f * s * (1.0f + erff(s * 0.70710678118654752f));
}

// ---------------- embedding gather -------------------------------------------
__global__ __launch_bounds__(256) void gather_kernel(
    const float* __restrict__ emb, const int* __restrict__ cap,
    float* __restrict__ out)
{
    int idx = blockIdx.x * 256 + threadIdx.x;
    int d  = idx & (ED_ - 1);
    int bs = idx >> 9;
    out[idx] = emb[(size_t)cap[bs] * ED_ + d];
}

// ---------------- 32x32 transpose: out[k][n] = in[n][k] ----------------------
__global__ __launch_bounds__(256) void transpose_k(
    const float* __restrict__ in, float* __restrict__ out, int N, int K)
{
    __shared__ float t[32][33];
    int k0 = blockIdx.x * 32, n0 = blockIdx.y * 32;
    int x = threadIdx.x & 31;
    int y = threadIdx.x >> 5;         // 0..7
    #pragma unroll
    for (int j = 0; j < 4; j++) {
        int n = y + 8 * j;
        t[n][x] = in[(size_t)(n0 + n) * K + k0 + x];
    }
    __syncthreads();
    #pragma unroll
    for (int j = 0; j < 4; j++) {
        int k = y + 8 * j;
        out[(size_t)(k0 + k) * N + n0 + x] = t[x][k];
    }
}

// ---------------- batched GEMV for M=32 (setup h0/c0 only) -------------------
__global__ __launch_bounds__(256) void gemvM32(
    const float* __restrict__ A, const float* __restrict__ W,
    const float* __restrict__ bias, float* __restrict__ C, int ldc, int K)
{
    __shared__ float sA[32][64];
    int tid = threadIdx.x, lane = tid & 31, w = tid >> 5;
    int n = blockIdx.x * 8 + w;
    const float* Wn = W + (size_t)n * K;
    float acc[32];
    #pragma unroll
    for (int b = 0; b < 32; b++) acc[b] = 0.f;
    for (int k0 = 0; k0 < K; k0 += 64) {
        __syncthreads();
        int kk = tid & 63, bb = tid >> 6;
        #pragma unroll
        for (int i = 0; i < 8; i++)
            sA[bb + i * 4][kk] = A[(size_t)(bb + i * 4) * K + k0 + kk];
        __syncthreads();
        float w0 = Wn[k0 + lane], w1 = Wn[k0 + 32 + lane];
        #pragma unroll
        for (int b = 0; b < 32; b++)
            acc[b] += w0 * sA[b][lane] + w1 * sA[b][lane + 32];
    }
    float out = 0.f;
    #pragma unroll
    for (int b = 0; b < 32; b++) {
        float v = acc[b];
        #pragma unroll
        for (int o = 16; o; o >>= 1) v += __shfl_xor_sync(0xffffffffu, v, o);
        if (lane == b) out = v;
    }
    C[(size_t)lane * (size_t)ldc + n] = out + bias[n];
}

// ---------------- 128x128 GEMM, cp.async 2-stage, f32x2 (n-packed) -----------
// C[M][N] = A[M][K] @ Wt[K][N] + bias ; A row-major (lda), Wt k-major (ldw).
__global__ __launch_bounds__(256, 2) void gemm_nn(
    const float* __restrict__ A, int lda,
    const float* __restrict__ Wt, int ldw,
    const float* __restrict__ bias,
    float* __restrict__ C, int ldc, int K)
{
    __shared__ float sA[2][128 * 20];    // [m][k] pitch 20
    __shared__ float sB[2][16 * 128];    // [k][n]
    int tid = threadIdx.x;
    int tx = tid & 15, ty = tid >> 4;
    int m0 = blockIdx.y * 128, n0 = blockIdx.x * 128;

    unsigned saU[2] = { su32(&sA[0][0]), su32(&sA[1][0]) };
    unsigned sbU[2] = { su32(&sB[0][0]), su32(&sB[1][0]) };

    // per-thread fixed chunk coords
    int ar0 = tid >> 2, ac0 = (tid & 3) * 4;             // A chunk 0: rows 0..63
    int br0 = tid >> 5, bc0 = (tid & 31) * 4;            // B chunk 0: k 0..7

    unsigned long long acc[8][4];
    #pragma unroll
    for (int i = 0; i < 8; i++)
        #pragma unroll
        for (int j = 0; j < 4; j++) acc[i][j] = 0ull;

    int KT = K >> 4;

    // tile loader
    auto load_tile = [&](int kt, int buf) {
        const float* a0 = A + (size_t)(m0 + ar0) * lda + kt * 16 + ac0;
        const float* a1 = A + (size_t)(m0 + ar0 + 64) * lda + kt * 16 + ac0;
        CP16(saU[buf] + (unsigned)((ar0 * 20 + ac0) * 4), a0);
        CP16(saU[buf] + (unsigned)(((ar0 + 64) * 20 + ac0) * 4), a1);
        const float* b0 = Wt + (size_t)(kt * 16 + br0) * ldw + n0 + bc0;
        const float* b1 = Wt + (size_t)(kt * 16 + br0 + 8) * ldw + n0 + bc0;
        CP16(sbU[buf] + (unsigned)((br0 * 128 + bc0) * 4), b0);
        CP16(sbU[buf] + (unsigned)(((br0 + 8) * 128 + bc0) * 4), b1);
    };

    load_tile(0, 0);
    CPCOMMIT();

    int buf = 0;
    for (int kt = 0; kt < KT; kt++) {
        if (kt + 1 < KT) {
            load_tile(kt + 1, buf ^ 1);
            CPCOMMIT();
            CPWAIT(1);
        } else {
            CPWAIT(0);
        }
        __syncthreads();
        {
            const float* pa = &sA[buf][0];
            const float* pb = &sB[buf][0];
            #pragma unroll
            for (int k4 = 0; k4 < 4; k4++) {
                float4 av[8];
                #pragma unroll
                for (int i = 0; i < 8; i++)
                    av[i] = *(const float4*)(pa + (ty * 8 + i) * 20 + k4 * 4);
                #pragma unroll
                for (int kk = 0; kk < 4; kk++) {
                    const float* bp = pb + (k4 * 4 + kk) * 128 + 4 * tx;
                    ulonglong2 bv0 = *(const ulonglong2*)(bp);
                    ulonglong2 bv1 = *(const ulonglong2*)(bp + 64);
                    #pragma unroll
                    for (int i = 0; i < 8; i++) {
                        float a = (kk == 0) ? av[i].x : (kk == 1) ? av[i].y
                                : (kk == 2) ? av[i].z : av[i].w;
                        unsigned long long ad = pack2(a, a);
                        fma2(acc[i][0], ad, bv0.x);
                        fma2(acc[i][1], ad, bv0.y);
                        fma2(acc[i][2], ad, bv1.x);
                        fma2(acc[i][3], ad, bv1.y);
                    }
                }
            }
        }
        __syncthreads();
        buf ^= 1;
    }

    // epilogue
    float4 bb0 = make_float4(0.f, 0.f, 0.f, 0.f);
    float4 bb1 = make_float4(0.f, 0.f, 0.f, 0.f);
    if (bias) {
        bb0 = *(const float4*)(bias + n0 + 4 * tx);
        bb1 = *(const float4*)(bias + n0 + 64 + 4 * tx);
    }
    #pragma unroll
    for (int i = 0; i < 8; i++) {
        size_t m = (size_t)(m0 + ty * 8 + i);
        float2 p0 = unpk2(acc[i][0]);
        float2 p1 = unpk2(acc[i][1]);
        float2 p2 = unpk2(acc[i][2]);
        float2 p3 = unpk2(acc[i][3]);
        float4 r0 = make_float4(p0.x + bb0.x, p0.y + bb0.y, p1.x + bb0.z, p1.y + bb0.w);
        float4 r1 = make_float4(p2.x + bb1.x, p2.y + bb1.y, p3.x + bb1.z, p3.y + bb1.w);
        *(float4*)(C + m * (size_t)ldc + n0 + 4 * tx)      = r0;
        *(float4*)(C + m * (size_t)ldc + n0 + 64 + 4 * tx) = r1;
    }
}

// ---------------- persistent recurrence kernel (round-7, unchanged) ----------
extern __shared__ float dsm[];

__device__ __forceinline__ void gemv_direct(
    const float* __restrict__ Ag, const float* sW,
    const float* __restrict__ bias, int n0,
    const float* __restrict__ addH,
    float* __restrict__ Cg, int tid)
{
    int lane = tid & 31, w = tid >> 5;
    unsigned long long acc[32];
    #pragma unroll
    for (int p = 0; p < 32; p++) acc[p] = 0ull;

    const float* xb = Ag + (size_t)(4 * w) * H_ + 4 * lane;
    #pragma unroll
    for (int c = 0; c < 8; c++) {
        ulonglong2 xv[4];
        #pragma unroll
        for (int b = 0; b < 4; b++)
            xv[b] = *(const ulonglong2*)(xb + (size_t)b * H_ + c * 128);
        #pragma unroll
        for (int n = 0; n < 8; n++) {
            ulonglong2 wv = *(const ulonglong2*)&sW[n * H_ + c * 128 + 4 * lane];
            #pragma unroll
            for (int b = 0; b < 4; b++) {
                fma2(acc[b * 8 + n], xv[b].x, wv.x);
                fma2(acc[b * 8 + n], xv[b].y, wv.y);
            }
        }
    }
    float outv = 0.f;
    #pragma unroll
    for (int p = 0; p < 32; p++) {
        float2 v = unpk2(acc[p]);
        float s = v.x + v.y;
        #pragma unroll
        for (int o = 16; o; o >>= 1) s += __shfl_xor_sync(0xffffffffu, s, o);
        if (lane == p) outv = s;
    }
    int bg = 4 * w + (lane >> 3);
    int ng = n0 + (lane & 7);
    float r = outv + bias[ng];
    if (addH) r += addH[(size_t)bg * H_ + ng];
    Cg[(size_t)bg * H_ + ng] = r;
}

__global__ __launch_bounds__(256, 1) void recurrence_kernel(
    const float* __restrict__ q_w,  const float* __restrict__ in_b,
    const float* __restrict__ out_w,const float* __restrict__ out_b,
    const float* __restrict__ w_hh, const float* __restrict__ b_hh,
    const float* __restrict__ ln_g, const float* __restrict__ ln_b2,
    const float* __restrict__ gK,   const float* __restrict__ gV,
    const float* __restrict__ gXp,
    float* gH, float* gC, float* gQ,
    float* gCtx, float* gO, float* gHall, float* attnb)
{
    __shared__ float sQ[1024];
    __shared__ float sScore[224];
    __shared__ float sProb[224];
    __shared__ float sred[8];
    __shared__ float sbc;
    __shared__ float sG[1024];
    __shared__ float sMu[32], sRs[32];

    float* SQW  = dsm;
    float* SOW  = dsm + 8192;
    float* SWH  = dsm + 16384;
    float* SLNG = dsm + 49152;
    float* SLNB = dsm + 50176;

    int tid = threadIdx.x, lane = tid & 31, w = tid >> 5;
    int bx = blockIdx.x;

    for (int i = tid; i < 8192; i += 256) {
        SQW[i] = q_w [(size_t)bx * 8192 + i];
        SOW[i] = out_w[(size_t)bx * 8192 + i];
    }
    for (int g = 0; g < 4; g++)
        for (int i = tid; i < 8192; i += 256)
            SWH[g * 8192 + i] = w_hh[((size_t)g * H_ + bx * 8) * H_ + i];
    for (int i = tid; i < 1024; i += 256) {
        SLNG[i] = ln_g[i];
        SLNB[i] = ln_b2[i];
    }
    __syncthreads();

    for (int t = 0; t < S_; t++) {
        gemv_direct(gH, SQW, in_b, bx * 8, nullptr, gQ, tid);
        grid_bar();

        if (bx < 32) {
            int b = bx;
            for (int i = tid; i < 1024; i += 256)
                sQ[i] = gQ[(size_t)b * H_ + i];
            __syncthreads();
            #pragma unroll 1
            for (int i = 0; i < 12; i++) {
                int n = i * 16 + w * 2;
                const float* kp0 = gK + ((size_t)b * NF_ + n) * H_;
                const float* kp1 = kp0 + H_;
                float s0 = 0.f, s1 = 0.f;
                #pragma unroll
                for (int j = 0; j < 8; j++) {
                    float4 q4  = *(const float4*)&sQ[4 * lane + 128 * j];
                    float4 k0v = *(const float4*)(kp0 + 4 * lane + 128 * j);
                    float4 k1v = *(const float4*)(kp1 + 4 * lane + 128 * j);
                    s0 += q4.x*k0v.x + q4.y*k0v.y + q4.z*k0v.z + q4.w*k0v.w;
                    s1 += q4.x*k1v.x + q4.y*k1v.y + q4.z*k1v.z + q4.w*k1v.w;
                }
                #pragma unroll
                for (int o = 16; o; o >>= 1) {
                    s0 += __shfl_xor_sync(0xffffffffu, s0, o);
                    s1 += __shfl_xor_sync(0xffffffffu, s1, o);
                }
                if (lane == 0) { sScore[n] = s0 * 0.03125f; sScore[n+1] = s1 * 0.03125f; }
            }
            if (w < 2) {
                int n = 192 + w * 2;
                const float* kp0 = gK + ((size_t)b * NF_ + n) * H_;
                const float* kp1 = kp0 + H_;
                float s0 = 0.f, s1 = 0.f;
                #pragma unroll
                for (int j = 0; j < 8; j++) {
                    float4 q4  = *(const float4*)&sQ[4 * lane + 128 * j];
                    float4 k0v = *(const float4*)(kp0 + 4 * lane + 128 * j);
                    float4 k1v = *(const float4*)(kp1 + 4 * lane + 128 * j);
                    s0 += q4.x*k0v.x + q4.y*k0v.y + q4.z*k0v.z + q4.w*k0v.w;
                    s1 += q4.x*k1v.x + q4.y*k1v.y + q4.z*k1v.z + q4.w*k1v.w;
                }
                #pragma unroll
                for (int o = 16; o; o >>= 1) {
                    s0 += __shfl_xor_sync(0xffffffffu, s0, o);
                    s1 += __shfl_xor_sync(0xffffffffu, s1, o);
                }
                if (lane == 0) { sScore[n] = s0 * 0.03125f; sScore[n+1] = s1 * 0.03125f; }
            }
            __syncthreads();
            float v = (tid < NF_) ? sScore[tid] : -FLT_MAX;
            float m = v;
            #pragma unroll
            for (int o = 16; o; o >>= 1) m = fmaxf(m, __shfl_xor_sync(0xffffffffu, m, o));
            if (lane == 0) sred[w] = m;
            __syncthreads();
            if (tid == 0) {
                float mm = sred[0];
                #pragma unroll
                for (int i = 1; i < 8; i++) mm = fmaxf(mm, sred[i]);
                sbc = mm;
            }
            __syncthreads();
            float e = (tid < NF_) ? expf(v - sbc) : 0.f;
            float s2 = e;
            #pragma unroll
            for (int o = 16; o; o >>= 1) s2 += __shfl_xor_sync(0xffffffffu, s2, o);
            if (lane == 0) sred[w] = s2;
            __syncthreads();
            if (tid == 0) {
                float ss = 0.f;
                #pragma unroll
                for (int i = 0; i < 8; i++) ss += sred[i];
                sbc = ss;
            }
            __syncthreads();
            float p = e / sbc;
            if (tid < NF_) {
                sProb[tid] = p;
                attnb[((size_t)b * S_ + t) * NF_ + tid] = p;
            }
            __syncthreads();
            {
                const float* vb = gV + (size_t)b * NF_ * H_ + tid * 4;
                float4 a = make_float4(0.f, 0.f, 0.f, 0.f);
                #pragma unroll 1
                for (int n0b = 0; n0b < 192; n0b += 8) {
                    float4 vv[8];
                    #pragma unroll
                    for (int j = 0; j < 8; j++)
                        vv[j] = *(const float4*)(vb + (size_t)(n0b + j) * H_);
                    #pragma unroll
                    for (int j = 0; j < 8; j++) {
                        float pp = sProb[n0b + j];
                        a.x += pp * vv[j].x; a.y += pp * vv[j].y;
                        a.z += pp * vv[j].z; a.w += pp * vv[j].w;
                    }
                }
                #pragma unroll
                for (int j = 0; j < 4; j++) {
                    float4 v4 = *(const float4*)(vb + (size_t)(192 + j) * H_);
                    float pp = sProb[192 + j];
                    a.x += pp * v4.x; a.y += pp * v4.y;
                    a.z += pp * v4.z; a.w += pp * v4.w;
                }
                *(float4*)(gCtx + (size_t)b * H_ + tid * 4) = a;
            }
        }
        grid_bar();

        gemv_direct(gCtx, SOW, out_b, bx * 8, gH, gO, tid);
        grid_bar();

        {
            {
                int b = tid >> 3, sl = tid & 7;
                const float* xb = gO + (size_t)b * H_ + sl * 4;
                float s = 0.f, s2 = 0.f;
                #pragma unroll 8
                for (int i = 0; i < 32; i++) {
                    float4 v = *(const float4*)(xb + i * 32);
                    s  += v.x + v.y + v.z + v.w;
                    s2 += v.x*v.x + v.y*v.y + v.z*v.z + v.w*v.w;
                }
                #pragma unroll
                for (int o2 = 1; o2 < 8; o2 <<= 1) {
                    s  += __shfl_xor_sync(0xffffffffu, s,  o2);
                    s2 += __shfl_xor_sync(0xffffffffu, s2, o2);
                }
                if (sl == 0) {
                    float mu = s * (1.0f / H_);
                    float var = s2 * (1.0f / H_) - mu * mu;
                    sMu[b] = mu;
                    sRs[b] = rsqrtf(var + 1e-5f);
                }
            }
            __syncthreads();

            const float* xb = gO + (size_t)(4 * w) * H_ + 4 * lane;
            float muv[4], rsv[4];
            #pragma unroll
            for (int b = 0; b < 4; b++) {
                muv[b] = sMu[4 * w + b];
                rsv[b] = sRs[4 * w + b];
            }

            #pragma unroll 1
            for (int p2 = 0; p2 < 2; p2++) {
                int g0 = 2 * p2, g1 = 2 * p2 + 1;
                const float* W0 = SWH + (size_t)g0 * 8192;
                const float* W1 = SWH + (size_t)g1 * 8192;
                unsigned long long aA[32], aB[32];
                #pragma unroll
                for (int p = 0; p < 32; p++) { aA[p] = 0ull; aB[p] = 0ull; }

                #pragma unroll
                for (int c = 0; c < 8; c++) {
                    float4 g4 = *(const float4*)&SLNG[c * 128 + 4 * lane];
                    float4 b4 = *(const float4*)&SLNB[c * 128 + 4 * lane];
                    ulonglong2 xn[4];
                    #pragma unroll
                    for (int b = 0; b < 4; b++) {
                        float4 x = *(const float4*)(xb + (size_t)b * H_ + c * 128);
                        float mu = muv[b], rs = rsv[b];
                        float4 r;
                        r.x = (x.x - mu) * rs * g4.x + b4.x;
                        r.y = (x.y - mu) * rs * g4.y + b4.y;
                        r.z = (x.z - mu) * rs * g4.z + b4.z;
                        r.w = (x.w - mu) * rs * g4.w + b4.w;
                        xn[b].x = pack2(r.x, r.y);
                        xn[b].y = pack2(r.z, r.w);
                    }
                    #pragma unroll
                    for (int n = 0; n < 8; n++) {
                        ulonglong2 w0 = *(const ulonglong2*)&W0[n * H_ + c * 128 + 4 * lane];
                        ulonglong2 w1 = *(const ulonglong2*)&W1[n * H_ + c * 128 + 4 * lane];
                        #pragma unroll
                        for (int b = 0; b < 4; b++) {
                            fma2(aA[b * 8 + n], xn[b].x, w0.x);
                            fma2(aA[b * 8 + n], xn[b].y, w0.y);
                            fma2(aB[b * 8 + n], xn[b].x, w1.x);
                            fma2(aB[b * 8 + n], xn[b].y, w1.y);
                        }
                    }
                }
                float oA = 0.f, oB = 0.f;
                #pragma unroll
                for (int p = 0; p < 32; p++) {
                    float2 va = unpk2(aA[p]);
                    float2 vb = unpk2(aB[p]);
                    float sa = va.x + va.y, sb2 = vb.x + vb.y;
                    #pragma unroll
                    for (int o = 16; o; o >>= 1) {
                        sa  += __shfl_xor_sync(0xffffffffu, sa,  o);
                        sb2 += __shfl_xor_sync(0xffffffffu, sb2, o);
                    }
                    if (lane == p) { oA = sa; oB = sb2; }
                }
                int bg = 4 * w + (lane >> 3);
                int c  = lane & 7;
                int nA = g0 * H_ + bx * 8 + c;
                int nB = g1 * H_ + bx * 8 + c;
                size_t xrow = ((size_t)bg * S_ + t) * (4 * H_);
                oA += b_hh[nA] + gXp[xrow + nA];
                oB += b_hh[nB] + gXp[xrow + nB];
                sG[g0 * 256 + c * 32 + bg] = oA;
                sG[g1 * 256 + c * 32 + bg] = oB;
            }
            __syncthreads();
            int b = tid & 31, jj = tid >> 5;
            int j2 = bx * 8 + jj;
            float ii = sG[0 * 256 + jj * 32 + b];
            float ff = sG[1 * 256 + jj * 32 + b];
            float gg = sG[2 * 256 + jj * 32 + b];
            float oo = sG[3 * 256 + jj * 32 + b];
            float si = 1.f / (1.f + expf(-ii));
            float sf = 1.f / (1.f + expf(-ff));
            float so = 1.f / (1.f + expf(-oo));
            float cn = sf * gC[b * H_ + j2] + si * tanhf(gg);
            float hn = so * tanhf(cn);
            gC[b * H_ + j2] = cn;
            gH[b * H_ + j2] = hn;
            gHall[((size_t)b * S_ + t) * H_ + j2] = hn;
        }
        grid_bar();
    }
}

// ---------------- orchestration ----------------------------------------------
extern "C" void kernel_launch(void* const* d_in, const int* in_sizes, int n_in,
                              void* d_out, int out_size)
{
    const float* features = (const float*)d_in[0];
    const int*   captions = (const int*)  d_in[1];
    const float* emb      = (const float*)d_in[2];
    const float* q_w      = (const float*)d_in[3];
    const float* k_w      = (const float*)d_in[4];
    const float* v_w      = (const float*)d_in[5];
    const float* in_b     = (const float*)d_in[6];
    const float* out_w    = (const float*)d_in[7];
    const float* out_b    = (const float*)d_in[8];
    const float* h0_w     = (const float*)d_in[9];
    const float* h0_b     = (const float*)d_in[10];
    const float* c0_w     = (const float*)d_in[11];
    const float* c0_b     = (const float*)d_in[12];
    const float* w_ih     = (const float*)d_in[13];
    const float* b_ih     = (const float*)d_in[14];
    const float* w_hh     = (const float*)d_in[15];
    const float* b_hh     = (const float*)d_in[16];
    const float* ln_g     = (const float*)d_in[17];
    const float* ln_b2    = (const float*)d_in[18];
    const float* lin_w    = (const float*)d_in[19];
    const float* lin_b    = (const float*)d_in[20];

    float* sc = nullptr;
    cudaGetSymbolAddress((void**)&sc, g_scratch);
    float* gK    = sc + OFF_K;
    float* gV    = sc + OFF_V;
    float* gMean = sc + OFF_MEAN;
    float* gH    = sc + OFF_H;
    float* gC    = sc + OFF_C;
    float* gQ    = sc + OFF_Q;
    float* gCtx  = sc + OFF_CTX;
    float* gO    = sc + OFF_O;
    float* gEmb  = sc + OFF_EMB;
    float* gXp   = sc + OFF_XP;
    float* gHall = sc + OFF_HALL;
    float* gAd   = sc + OFF_AD;
    float* gKT   = sc + OFF_KT;
    float* gVT   = sc + OFF_VT;
    float* gWIT  = sc + OFF_WIT;
    float* gLWT  = sc + OFF_LWT;

    float* out   = (float*)d_out;
    float* preds = out;
    const size_t PRED = (size_t)B_ * S_ * V_;
    bool wa = ((size_t)out_size >= PRED + (size_t)B_ * S_ * NF_);
    float* attnb = wa ? (out + PRED) : gAd;

    const int REC_SMEM = 51200 * 4;   // SQW+SOW+SWH+SLNG+SLNB = 200 KB
    cudaFuncSetAttribute(recurrence_kernel,
                         cudaFuncAttributeMaxDynamicSharedMemorySize, REC_SMEM);

    // ---- weight transposes (K-major for cp.async GEMM) ----
    transpose_k<<<dim3(ENC_ / 32, H_ / 32), 256>>>(k_w,  gKT,  H_,     ENC_);
    transpose_k<<<dim3(ENC_ / 32, H_ / 32), 256>>>(v_w,  gVT,  H_,     ENC_);
    transpose_k<<<dim3(ED_  / 32, 4 * H_ / 32), 256>>>(w_ih, gWIT, 4 * H_, ED_);
    transpose_k<<<dim3(H_   / 32, V_ / 32), 256>>>(lin_w, gLWT, V_,    H_);

    // ---- setup (hoisted) ----
    mean_gelu_kernel<<<dim3(ENC_ / 256, B_), 256>>>(features, gMean);
    gemvM32<<<H_ / 8, 256>>>(gMean, h0_w, h0_b, gH, H_, ENC_);
    gemvM32<<<H_ / 8, 256>>>(gMean, c0_w, c0_b, gC, H_, ENC_);
    gemm_nn<<<dim3(H_ / 128, (B_ * NF_) / 128), 256>>>(
        features, ENC_, gKT, H_, in_b + H_,     gK, H_, ENC_);
    gemm_nn<<<dim3(H_ / 128, (B_ * NF_) / 128), 256>>>(
        features, ENC_, gVT, H_, in_b + 2 * H_, gV, H_, ENC_);
    gather_kernel<<<(B_ * S_ * ED_) / 256, 256>>>(emb, captions, gEmb);
    gemm_nn<<<dim3((4 * H_) / 128, (B_ * S_) / 128), 256>>>(
        gEmb, ED_, gWIT, 4 * H_, b_ih, gXp, 4 * H_, ED_);

    // ---- recurrence in one persistent kernel ----
    recurrence_kernel<<<NB_, 256, REC_SMEM>>>(
        q_w, in_b, out_w, out_b, w_hh, b_hh, ln_g, ln_b2,
        gK, gV, gXp, gH, gC, gQ, gCtx, gO, gHall, attnb);

    // ---- batched logits ----
    gemm_nn<<<dim3(V_ / 128, (B_ * S_) / 128), 256>>>(
        gHall, H_, gLWT, V_, lin_b, preds, V_, H_);
}

// round 12
// speedup vs baseline: 2.2186x; 1.3588x over previous
#include <cuda_runtime.h>
#include <cuda_bf16.h>
#include <math.h>
#include <float.h>

#define B_   32
#define NF_  196
#define ENC_ 2048
#define V_   32000
#define ED_  512
#define S_   32
#define H_   1024
#define NB_  128        // persistent grid size (all co-resident on 148 SMs)

// ---------------- f32x2 packed helpers (sm_103a) -----------------------------
__device__ __forceinline__ void fma2(unsigned long long& d,
                                     unsigned long long a, unsigned long long b) {
    asm("fma.rn.f32x2 %0, %1, %2, %0;" : "+l"(d) : "l"(a), "l"(b));
}
__device__ __forceinline__ unsigned long long pack2(float lo, float hi) {
    unsigned long long r;
    asm("mov.b64 %0, {%1, %2};" : "=l"(r) : "f"(lo), "f"(hi));
    return r;
}
__device__ __forceinline__ float2 unpk2(unsigned long long v) {
    float2 r;
    asm("mov.b64 {%0, %1}, %2;" : "=f"(r.x), "=f"(r.y) : "l"(v));
    return r;
}

// ---------------- scratch ----------------------------------------------------
static constexpr size_t SZ_K    = (size_t)B_ * NF_ * H_;
static constexpr size_t OFF_K   = 0;
static constexpr size_t OFF_V   = OFF_K + SZ_K;
static constexpr size_t OFF_MEAN= OFF_V + SZ_K;
static constexpr size_t OFF_H   = OFF_MEAN + (size_t)B_ * ENC_;
static constexpr size_t OFF_C   = OFF_H   + (size_t)B_ * H_;
static constexpr size_t OFF_Q   = OFF_C   + (size_t)B_ * H_;
static constexpr size_t OFF_CTX = OFF_Q   + (size_t)B_ * H_;
static constexpr size_t OFF_O   = OFF_CTX + (size_t)B_ * H_;
static constexpr size_t OFF_EMB = OFF_O   + (size_t)B_ * H_;
static constexpr size_t OFF_XP  = OFF_EMB + (size_t)B_ * S_ * ED_;
static constexpr size_t OFF_HALL= OFF_XP  + (size_t)B_ * S_ * 4 * H_;
static constexpr size_t OFF_AD  = OFF_HALL+ (size_t)B_ * S_ * H_;
static constexpr size_t TOTAL_F = OFF_AD  + (size_t)B_ * S_ * NF_;

__device__ float g_scratch[TOTAL_F];
__device__ unsigned g_bar_count = 0;
__device__ unsigned g_bar_gen   = 0;

// ---------------- grid-wide barrier ------------------------------------------
__device__ __forceinline__ void grid_bar() {
    __syncthreads();
    if (threadIdx.x == 0) {
        __threadfence();
        unsigned gen = *(volatile unsigned*)&g_bar_gen;
        unsigned a = atomicAdd(&g_bar_count, 1u);
        if (a == NB_ - 1) {
            atomicExch(&g_bar_count, 0u);
            __threadfence();
            atomicAdd(&g_bar_gen, 1u);
        } else {
            while (*(volatile unsigned*)&g_bar_gen == gen) __nanosleep(64);
        }
        __threadfence();
    }
    __syncthreads();
}

// ---------------- mean over N + exact gelu -----------------------------------
__global__ __launch_bounds__(256) void mean_gelu_kernel(
    const float* __restrict__ feat, float* __restrict__ outMean)
{
    int b = blockIdx.y;
    int e = blockIdx.x * 256 + threadIdx.x;
    const float* p = feat + (size_t)b * NF_ * ENC_ + e;
    float s = 0.f;
    #pragma unroll 4
    for (int n = 0; n < NF_; n++) s += p[(size_t)n * ENC_];
    s *= (1.0f / (float)NF_);
    outMean[(size_t)b * ENC_ + e] = 0.5f * s * (1.0f + erff(s * 0.70710678118654752f));
}

// ---------------- embedding gather -------------------------------------------
__global__ __launch_bounds__(256) void gather_kernel(
    const float* __restrict__ emb, const int* __restrict__ cap,
    float* __restrict__ out)
{
    int idx = blockIdx.x * 256 + threadIdx.x;
    int d  = idx & (ED_ - 1);
    int bs = idx >> 9;
    out[idx] = emb[(size_t)cap[bs] * ED_ + d];
}

// ---------------- batched GEMV for M=32 (setup h0/c0 only) -------------------
__global__ __launch_bounds__(256) void gemvM32(
    const float* __restrict__ A, const float* __restrict__ W,
    const float* __restrict__ bias, float* __restrict__ C, int ldc, int K)
{
    __shared__ float sA[32][64];
    int tid = threadIdx.x, lane = tid & 31, w = tid >> 5;
    int n = blockIdx.x * 8 + w;
    const float* Wn = W + (size_t)n * K;
    float acc[32];
    #pragma unroll
    for (int b = 0; b < 32; b++) acc[b] = 0.f;
    for (int k0 = 0; k0 < K; k0 += 64) {
        __syncthreads();
        int kk = tid & 63, bb = tid >> 6;
        #pragma unroll
        for (int i = 0; i < 8; i++)
            sA[bb + i * 4][kk] = A[(size_t)(bb + i * 4) * K + k0 + kk];
        __syncthreads();
        float w0 = Wn[k0 + lane], w1 = Wn[k0 + 32 + lane];
        #pragma unroll
        for (int b = 0; b < 32; b++)
            acc[b] += w0 * sA[b][lane] + w1 * sA[b][lane + 32];
    }
    float out = 0.f;
    #pragma unroll
    for (int b = 0; b < 32; b++) {
        float v = acc[b];
        #pragma unroll
        for (int o = 16; o; o >>= 1) v += __shfl_xor_sync(0xffffffffu, v, o);
        if (lane == b) out = v;
    }
    C[(size_t)lane * (size_t)ldc + n] = out + bias[n];
}

// ---------------- mma.sync bf16x3 GEMM ---------------------------------------
// C[M][N] = A[M][K] @ W[N][K]^T + bias  (fp32 in/out; bf16 hi/lo split; fp32 acc)
// block: 256 thr = 8 warps (4M x 2N); tile 128x64; warp tile 32x32; K-chunk 32.
// smem pitch 20 b32 per row (80 B: 16B-aligned, conflict-free fragment loads).
#define MMA16816(d, a, b) \
    asm volatile("mma.sync.aligned.m16n8k16.row.col.f32.bf16.bf16.f32 " \
        "{%0,%1,%2,%3}, {%4,%5,%6,%7}, {%8,%9}, {%0,%1,%2,%3};" \
        : "+f"((d)[0]), "+f"((d)[1]), "+f"((d)[2]), "+f"((d)[3]) \
        : "r"((a)[0]), "r"((a)[1]), "r"((a)[2]), "r"((a)[3]), \
          "r"((b)[0]), "r"((b)[1]))

__device__ __forceinline__ void cvt8(
    const float* __restrict__ src, unsigned* dh, unsigned* dl)
{
    float4 x0 = *(const float4*)(src);
    float4 x1 = *(const float4*)(src + 4);
    unsigned h[4], l[4];
    asm("cvt.rn.bf16x2.f32 %0, %1, %2;" : "=r"(h[0]) : "f"(x0.y), "f"(x0.x));
    asm("cvt.rn.bf16x2.f32 %0, %1, %2;" : "=r"(h[1]) : "f"(x0.w), "f"(x0.z));
    asm("cvt.rn.bf16x2.f32 %0, %1, %2;" : "=r"(h[2]) : "f"(x1.y), "f"(x1.x));
    asm("cvt.rn.bf16x2.f32 %0, %1, %2;" : "=r"(h[3]) : "f"(x1.w), "f"(x1.z));
    float r0 = x0.x - __uint_as_float(h[0] << 16);
    float r1 = x0.y - __uint_as_float(h[0] & 0xffff0000u);
    float r2 = x0.z - __uint_as_float(h[1] << 16);
    float r3 = x0.w - __uint_as_float(h[1] & 0xffff0000u);
    float r4 = x1.x - __uint_as_float(h[2] << 16);
    float r5 = x1.y - __uint_as_float(h[2] & 0xffff0000u);
    float r6 = x1.z - __uint_as_float(h[3] << 16);
    float r7 = x1.w - __uint_as_float(h[3] & 0xffff0000u);
    asm("cvt.rn.bf16x2.f32 %0, %1, %2;" : "=r"(l[0]) : "f"(r1), "f"(r0));
    asm("cvt.rn.bf16x2.f32 %0, %1, %2;" : "=r"(l[1]) : "f"(r3), "f"(r2));
    asm("cvt.rn.bf16x2.f32 %0, %1, %2;" : "=r"(l[2]) : "f"(r5), "f"(r4));
    asm("cvt.rn.bf16x2.f32 %0, %1, %2;" : "=r"(l[3]) : "f"(r7), "f"(r6));
    *(uint4*)dh = make_uint4(h[0], h[1], h[2], h[3]);
    *(uint4*)dl = make_uint4(l[0], l[1], l[2], l[3]);
}

__global__ __launch_bounds__(256) void mma_gemm(
    const float* __restrict__ A, int lda,
    const float* __restrict__ W,          // [N][K] row-major
    const float* __restrict__ bias,
    float* __restrict__ C, int ldc, int K)
{
    __shared__ unsigned sAh[128 * 20], sAl[128 * 20];
    __shared__ unsigned sBh[64 * 20],  sBl[64 * 20];

    int tid = threadIdx.x, lane = tid & 31, wid = tid >> 5;
    int wm = wid & 3, wn = wid >> 2;          // warp grid 4(M) x 2(N)
    int g = lane >> 2, tig = lane & 3;
    int m0 = blockIdx.y * 128, n0 = blockIdx.x * 64;

    float acc[2][4][4];
    #pragma unroll
    for (int mt = 0; mt < 2; mt++)
        #pragma unroll
        for (int nt = 0; nt < 4; nt++)
            #pragma unroll
            for (int i = 0; i < 4; i++) acc[mt][nt][i] = 0.f;

    // A conversion coords: thread -> row tid>>1, k-half tid&1 (16 elems)
    int arow = tid >> 1, ahalf = tid & 1;
    // B conversion coords: thread -> row tid>>2, k-quarter tid&3 (8 elems)
    int brow = tid >> 2, bq = tid & 3;

    int nchunks = K >> 5;
    for (int c = 0; c < nchunks; c++) {
        __syncthreads();
        {
            const float* ar = A + (size_t)(m0 + arow) * lda + c * 32 + ahalf * 16;
            unsigned off = (unsigned)(arow * 20 + ahalf * 8);
            cvt8(ar,     sAh + off,     sAl + off);
            cvt8(ar + 8, sAh + off + 4, sAl + off + 4);
        }
        {
            const float* br = W + (size_t)(n0 + brow) * K + c * 32 + bq * 8;
            unsigned off = (unsigned)(brow * 20 + bq * 4);
            cvt8(br, sBh + off, sBl + off);
        }
        __syncthreads();

        #pragma unroll
        for (int ks = 0; ks < 2; ks++) {
            unsigned ah[2][4], al[2][4], bh[4][2], bl[4][2];
            #pragma unroll
            for (int mt = 0; mt < 2; mt++) {
                int r = wm * 32 + mt * 16 + g;
                int base = r * 20 + ks * 8 + tig;
                ah[mt][0] = sAh[base];
                ah[mt][1] = sAh[base + 160];       // row + 8
                ah[mt][2] = sAh[base + 4];         // k + 8
                ah[mt][3] = sAh[base + 164];
                al[mt][0] = sAl[base];
                al[mt][1] = sAl[base + 160];
                al[mt][2] = sAl[base + 4];
                al[mt][3] = sAl[base + 164];
            }
            #pragma unroll
            for (int nt = 0; nt < 4; nt++) {
                int n = wn * 32 + nt * 8 + g;
                int base = n * 20 + ks * 8 + tig;
                bh[nt][0] = sBh[base];
                bh[nt][1] = sBh[base + 4];
                bl[nt][0] = sBl[base];
                bl[nt][1] = sBl[base + 4];
            }
            #pragma unroll
            for (int mt = 0; mt < 2; mt++)
                #pragma unroll
                for (int nt = 0; nt < 4; nt++) {
                    MMA16816(acc[mt][nt], ah[mt], bh[nt]);
                    MMA16816(acc[mt][nt], ah[mt], bl[nt]);
                    MMA16816(acc[mt][nt], al[mt], bh[nt]);
                }
        }
    }

    // epilogue
    #pragma unroll
    for (int mt = 0; mt < 2; mt++) {
        int row = m0 + wm * 32 + mt * 16 + g;
        #pragma unroll
        for (int nt = 0; nt < 4; nt++) {
            int col = n0 + wn * 32 + nt * 8 + 2 * tig;
            float2 bb = *(const float2*)(bias + col);
            float2 r0 = make_float2(acc[mt][nt][0] + bb.x, acc[mt][nt][1] + bb.y);
            float2 r1 = make_float2(acc[mt][nt][2] + bb.x, acc[mt][nt][3] + bb.y);
            *(float2*)(C + (size_t)row * ldc + col)       = r0;
            *(float2*)(C + (size_t)(row + 8) * ldc + col) = r1;
        }
    }
}

// ---------------- persistent recurrence kernel (round-7/8, unchanged) --------
extern __shared__ float dsm[];

__device__ __forceinline__ void gemv_direct(
    const float* __restrict__ Ag, const float* sW,
    const float* __restrict__ bias, int n0,
    const float* __restrict__ addH,
    float* __restrict__ Cg, int tid)
{
    int lane = tid & 31, w = tid >> 5;
    unsigned long long acc[32];
    #pragma unroll
    for (int p = 0; p < 32; p++) acc[p] = 0ull;

    const float* xb = Ag + (size_t)(4 * w) * H_ + 4 * lane;
    #pragma unroll
    for (int c = 0; c < 8; c++) {
        ulonglong2 xv[4];
        #pragma unroll
        for (int b = 0; b < 4; b++)
            xv[b] = *(const ulonglong2*)(xb + (size_t)b * H_ + c * 128);
        #pragma unroll
        for (int n = 0; n < 8; n++) {
            ulonglong2 wv = *(const ulonglong2*)&sW[n * H_ + c * 128 + 4 * lane];
            #pragma unroll
            for (int b = 0; b < 4; b++) {
                fma2(acc[b * 8 + n], xv[b].x, wv.x);
                fma2(acc[b * 8 + n], xv[b].y, wv.y);
            }
        }
    }
    float outv = 0.f;
    #pragma unroll
    for (int p = 0; p < 32; p++) {
        float2 v = unpk2(acc[p]);
        float s = v.x + v.y;
        #pragma unroll
        for (int o = 16; o; o >>= 1) s += __shfl_xor_sync(0xffffffffu, s, o);
        if (lane == p) outv = s;
    }
    int bg = 4 * w + (lane >> 3);
    int ng = n0 + (lane & 7);
    float r = outv + bias[ng];
    if (addH) r += addH[(size_t)bg * H_ + ng];
    Cg[(size_t)bg * H_ + ng] = r;
}

__global__ __launch_bounds__(256, 1) void recurrence_kernel(
    const float* __restrict__ q_w,  const float* __restrict__ in_b,
    const float* __restrict__ out_w,const float* __restrict__ out_b,
    const float* __restrict__ w_hh, const float* __restrict__ b_hh,
    const float* __restrict__ ln_g, const float* __restrict__ ln_b2,
    const float* __restrict__ gK,   const float* __restrict__ gV,
    const float* __restrict__ gXp,
    float* gH, float* gC, float* gQ,
    float* gCtx, float* gO, float* gHall, float* attnb)
{
    __shared__ float sQ[1024];
    __shared__ float sScore[224];
    __shared__ float sProb[224];
    __shared__ float sred[8];
    __shared__ float sbc;
    __shared__ float sG[1024];
    __shared__ float sMu[32], sRs[32];

    float* SQW  = dsm;
    float* SOW  = dsm + 8192;
    float* SWH  = dsm + 16384;
    float* SLNG = dsm + 49152;
    float* SLNB = dsm + 50176;

    int tid = threadIdx.x, lane = tid & 31, w = tid >> 5;
    int bx = blockIdx.x;

    for (int i = tid; i < 8192; i += 256) {
        SQW[i] = q_w [(size_t)bx * 8192 + i];
        SOW[i] = out_w[(size_t)bx * 8192 + i];
    }
    for (int g = 0; g < 4; g++)
        for (int i = tid; i < 8192; i += 256)
            SWH[g * 8192 + i] = w_hh[((size_t)g * H_ + bx * 8) * H_ + i];
    for (int i = tid; i < 1024; i += 256) {
        SLNG[i] = ln_g[i];
        SLNB[i] = ln_b2[i];
    }
    __syncthreads();

    for (int t = 0; t < S_; t++) {
        gemv_direct(gH, SQW, in_b, bx * 8, nullptr, gQ, tid);
        grid_bar();

        if (bx < 32) {
            int b = bx;
            for (int i = tid; i < 1024; i += 256)
                sQ[i] = gQ[(size_t)b * H_ + i];
            __syncthreads();
            #pragma unroll 1
            for (int i = 0; i < 12; i++) {
                int n = i * 16 + w * 2;
                const float* kp0 = gK + ((size_t)b * NF_ + n) * H_;
                const float* kp1 = kp0 + H_;
                float s0 = 0.f, s1 = 0.f;
                #pragma unroll
                for (int j = 0; j < 8; j++) {
                    float4 q4  = *(const float4*)&sQ[4 * lane + 128 * j];
                    float4 k0v = *(const float4*)(kp0 + 4 * lane + 128 * j);
                    float4 k1v = *(const float4*)(kp1 + 4 * lane + 128 * j);
                    s0 += q4.x*k0v.x + q4.y*k0v.y + q4.z*k0v.z + q4.w*k0v.w;
                    s1 += q4.x*k1v.x + q4.y*k1v.y + q4.z*k1v.z + q4.w*k1v.w;
                }
                #pragma unroll
                for (int o = 16; o; o >>= 1) {
                    s0 += __shfl_xor_sync(0xffffffffu, s0, o);
                    s1 += __shfl_xor_sync(0xffffffffu, s1, o);
                }
                if (lane == 0) { sScore[n] = s0 * 0.03125f; sScore[n+1] = s1 * 0.03125f; }
            }
            if (w < 2) {
                int n = 192 + w * 2;
                const float* kp0 = gK + ((size_t)b * NF_ + n) * H_;
                const float* kp1 = kp0 + H_;
                float s0 = 0.f, s1 = 0.f;
                #pragma unroll
                for (int j = 0; j < 8; j++) {
                    float4 q4  = *(const float4*)&sQ[4 * lane + 128 * j];
                    float4 k0v = *(const float4*)(kp0 + 4 * lane + 128 * j);
                    float4 k1v = *(const float4*)(kp1 + 4 * lane + 128 * j);
                    s0 += q4.x*k0v.x + q4.y*k0v.y + q4.z*k0v.z + q4.w*k0v.w;
                    s1 += q4.x*k1v.x + q4.y*k1v.y + q4.z*k1v.z + q4.w*k1v.w;
                }
                #pragma unroll
                for (int o = 16; o; o >>= 1) {
                    s0 += __shfl_xor_sync(0xffffffffu, s0, o);
                    s1 += __shfl_xor_sync(0xffffffffu, s1, o);
                }
                if (lane == 0) { sScore[n] = s0 * 0.03125f; sScore[n+1] = s1 * 0.03125f; }
            }
            __syncthreads();
            float v = (tid < NF_) ? sScore[tid] : -FLT_MAX;
            float m = v;
            #pragma unroll
            for (int o = 16; o; o >>= 1) m = fmaxf(m, __shfl_xor_sync(0xffffffffu, m, o));
            if (lane == 0) sred[w] = m;
            __syncthreads();
            if (tid == 0) {
                float mm = sred[0];
                #pragma unroll
                for (int i = 1; i < 8; i++) mm = fmaxf(mm, sred[i]);
                sbc = mm;
            }
            __syncthreads();
            float e = (tid < NF_) ? expf(v - sbc) : 0.f;
            float s2 = e;
            #pragma unroll
            for (int o = 16; o; o >>= 1) s2 += __shfl_xor_sync(0xffffffffu, s2, o);
            if (lane == 0) sred[w] = s2;
            __syncthreads();
            if (tid == 0) {
                float ss = 0.f;
                #pragma unroll
                for (int i = 0; i < 8; i++) ss += sred[i];
                sbc = ss;
            }
            __syncthreads();
            float p = e / sbc;
            if (tid < NF_) {
                sProb[tid] = p;
                attnb[((size_t)b * S_ + t) * NF_ + tid] = p;
            }
            __syncthreads();
            {
                const float* vb = gV + (size_t)b * NF_ * H_ + tid * 4;
                float4 a = make_float4(0.f, 0.f, 0.f, 0.f);
                #pragma unroll 1
                for (int n0b = 0; n0b < 192; n0b += 8) {
                    float4 vv[8];
                    #pragma unroll
                    for (int j = 0; j < 8; j++)
                        vv[j] = *(const float4*)(vb + (size_t)(n0b + j) * H_);
                    #pragma unroll
                    for (int j = 0; j < 8; j++) {
                        float pp = sProb[n0b + j];
                        a.x += pp * vv[j].x; a.y += pp * vv[j].y;
                        a.z += pp * vv[j].z; a.w += pp * vv[j].w;
                    }
                }
                #pragma unroll
                for (int j = 0; j < 4; j++) {
                    float4 v4 = *(const float4*)(vb + (size_t)(192 + j) * H_);
                    float pp = sProb[192 + j];
                    a.x += pp * v4.x; a.y += pp * v4.y;
                    a.z += pp * v4.z; a.w += pp * v4.w;
                }
                *(float4*)(gCtx + (size_t)b * H_ + tid * 4) = a;
            }
        }
        grid_bar();

        gemv_direct(gCtx, SOW, out_b, bx * 8, gH, gO, tid);
        grid_bar();

        {
            {
                int b = tid >> 3, sl = tid & 7;
                const float* xb = gO + (size_t)b * H_ + sl * 4;
                float s = 0.f, s2 = 0.f;
                #pragma unroll 8
                for (int i = 0; i < 32; i++) {
                    float4 v = *(const float4*)(xb + i * 32);
                    s  += v.x + v.y + v.z + v.w;
                    s2 += v.x*v.x + v.y*v.y + v.z*v.z + v.w*v.w;
                }
                #pragma unroll
                for (int o2 = 1; o2 < 8; o2 <<= 1) {
                    s  += __shfl_xor_sync(0xffffffffu, s,  o2);
                    s2 += __shfl_xor_sync(0xffffffffu, s2, o2);
                }
                if (sl == 0) {
                    float mu = s * (1.0f / H_);
                    float var = s2 * (1.0f / H_) - mu * mu;
                    sMu[b] = mu;
                    sRs[b] = rsqrtf(var + 1e-5f);
                }
            }
            __syncthreads();

            const float* xb = gO + (size_t)(4 * w) * H_ + 4 * lane;
            float muv[4], rsv[4];
            #pragma unroll
            for (int b = 0; b < 4; b++) {
                muv[b] = sMu[4 * w + b];
                rsv[b] = sRs[4 * w + b];
            }

            #pragma unroll 1
            for (int p2 = 0; p2 < 2; p2++) {
                int g0 = 2 * p2, g1 = 2 * p2 + 1;
                const float* W0 = SWH + (size_t)g0 * 8192;
                const float* W1 = SWH + (size_t)g1 * 8192;
                unsigned long long aA[32], aB[32];
                #pragma unroll
                for (int p = 0; p < 32; p++) { aA[p] = 0ull; aB[p] = 0ull; }

                #pragma unroll
                for (int c = 0; c < 8; c++) {
                    float4 g4 = *(const float4*)&SLNG[c * 128 + 4 * lane];
                    float4 b4 = *(const float4*)&SLNB[c * 128 + 4 * lane];
                    ulonglong2 xn[4];
                    #pragma unroll
                    for (int b = 0; b < 4; b++) {
                        float4 x = *(const float4*)(xb + (size_t)b * H_ + c * 128);
                        float mu = muv[b], rs = rsv[b];
                        float4 r;
                        r.x = (x.x - mu) * rs * g4.x + b4.x;
                        r.y = (x.y - mu) * rs * g4.y + b4.y;
                        r.z = (x.z - mu) * rs * g4.z + b4.z;
                        r.w = (x.w - mu) * rs * g4.w + b4.w;
                        xn[b].x = pack2(r.x, r.y);
                        xn[b].y = pack2(r.z, r.w);
                    }
                    #pragma unroll
                    for (int n = 0; n < 8; n++) {
                        ulonglong2 w0 = *(const ulonglong2*)&W0[n * H_ + c * 128 + 4 * lane];
                        ulonglong2 w1 = *(const ulonglong2*)&W1[n * H_ + c * 128 + 4 * lane];
                        #pragma unroll
                        for (int b = 0; b < 4; b++) {
                            fma2(aA[b * 8 + n], xn[b].x, w0.x);
                            fma2(aA[b * 8 + n], xn[b].y, w0.y);
                            fma2(aB[b * 8 + n], xn[b].x, w1.x);
                            fma2(aB[b * 8 + n], xn[b].y, w1.y);
                        }
                    }
                }
                float oA = 0.f, oB = 0.f;
                #pragma unroll
                for (int p = 0; p < 32; p++) {
                    float2 va = unpk2(aA[p]);
                    float2 vb = unpk2(aB[p]);
                    float sa = va.x + va.y, sb2 = vb.x + vb.y;
                    #pragma unroll
                    for (int o = 16; o; o >>= 1) {
                        sa  += __shfl_xor_sync(0xffffffffu, sa,  o);
                        sb2 += __shfl_xor_sync(0xffffffffu, sb2, o);
                    }
                    if (lane == p) { oA = sa; oB = sb2; }
                }
                int bg = 4 * w + (lane >> 3);
                int c  = lane & 7;
                int nA = g0 * H_ + bx * 8 + c;
                int nB = g1 * H_ + bx * 8 + c;
                size_t xrow = ((size_t)bg * S_ + t) * (4 * H_);
                oA += b_hh[nA] + gXp[xrow + nA];
                oB += b_hh[nB] + gXp[xrow + nB];
                sG[g0 * 256 + c * 32 + bg] = oA;
                sG[g1 * 256 + c * 32 + bg] = oB;
            }
            __syncthreads();
            int b = tid & 31, jj = tid >> 5;
            int j2 = bx * 8 + jj;
            float ii = sG[0 * 256 + jj * 32 + b];
            float ff = sG[1 * 256 + jj * 32 + b];
            float gg = sG[2 * 256 + jj * 32 + b];
            float oo = sG[3 * 256 + jj * 32 + b];
            float si = 1.f / (1.f + expf(-ii));
            float sf = 1.f / (1.f + expf(-ff));
            float so = 1.f / (1.f + expf(-oo));
            float cn = sf * gC[b * H_ + j2] + si * tanhf(gg);
            float hn = so * tanhf(cn);
            gC[b * H_ + j2] = cn;
            gH[b * H_ + j2] = hn;
            gHall[((size_t)b * S_ + t) * H_ + j2] = hn;
        }
        grid_bar();
    }
}

// ---------------- orchestration ----------------------------------------------
extern "C" void kernel_launch(void* const* d_in, const int* in_sizes, int n_in,
                              void* d_out, int out_size)
{
    const float* features = (const float*)d_in[0];
    const int*   captions = (const int*)  d_in[1];
    const float* emb      = (const float*)d_in[2];
    const float* q_w      = (const float*)d_in[3];
    const float* k_w      = (const float*)d_in[4];
    const float* v_w      = (const float*)d_in[5];
    const float* in_b     = (const float*)d_in[6];
    const float* out_w    = (const float*)d_in[7];
    const float* out_b    = (const float*)d_in[8];
    const float* h0_w     = (const float*)d_in[9];
    const float* h0_b     = (const float*)d_in[10];
    const float* c0_w     = (const float*)d_in[11];
    const float* c0_b     = (const float*)d_in[12];
    const float* w_ih     = (const float*)d_in[13];
    const float* b_ih     = (const float*)d_in[14];
    const float* w_hh     = (const float*)d_in[15];
    const float* b_hh     = (const float*)d_in[16];
    const float* ln_g     = (const float*)d_in[17];
    const float* ln_b2    = (const float*)d_in[18];
    const float* lin_w    = (const float*)d_in[19];
    const float* lin_b    = (const float*)d_in[20];

    float* sc = nullptr;
    cudaGetSymbolAddress((void**)&sc, g_scratch);
    float* gK    = sc + OFF_K;
    float* gV    = sc + OFF_V;
    float* gMean = sc + OFF_MEAN;
    float* gH    = sc + OFF_H;
    float* gC    = sc + OFF_C;
    float* gQ    = sc + OFF_Q;
    float* gCtx  = sc + OFF_CTX;
    float* gO    = sc + OFF_O;
    float* gEmb  = sc + OFF_EMB;
    float* gXp   = sc + OFF_XP;
    float* gHall = sc + OFF_HALL;
    float* gAd   = sc + OFF_AD;

    float* out   = (float*)d_out;
    float* preds = out;
    const size_t PRED = (size_t)B_ * S_ * V_;
    bool wa = ((size_t)out_size >= PRED + (size_t)B_ * S_ * NF_);
    float* attnb = wa ? (out + PRED) : gAd;

    const int REC_SMEM = 51200 * 4;   // 200 KB for recurrence
    cudaFuncSetAttribute(recurrence_kernel,
                         cudaFuncAttributeMaxDynamicSharedMemorySize, REC_SMEM);

    // ---- setup (hoisted) ----
    mean_gelu_kernel<<<dim3(ENC_ / 256, B_), 256>>>(features, gMean);
    gemvM32<<<H_ / 8, 256>>>(gMean, h0_w, h0_b, gH, H_, ENC_);
    gemvM32<<<H_ / 8, 256>>>(gMean, c0_w, c0_b, gC, H_, ENC_);
    mma_gemm<<<dim3(H_ / 64, (B_ * NF_) / 128), 256>>>(
        features, ENC_, k_w, in_b + H_,     gK, H_, ENC_);
    mma_gemm<<<dim3(H_ / 64, (B_ * NF_) / 128), 256>>>(
        features, ENC_, v_w, in_b + 2 * H_, gV, H_, ENC_);
    gather_kernel<<<(B_ * S_ * ED_) / 256, 256>>>(emb, captions, gEmb);
    mma_gemm<<<dim3((4 * H_) / 64, (B_ * S_) / 128), 256>>>(
        gEmb, ED_, w_ih, b_ih, gXp, 4 * H_, ED_);

    // ---- recurrence in one persistent kernel ----
    recurrence_kernel<<<NB_, 256, REC_SMEM>>>(
        q_w, in_b, out_w, out_b, w_hh, b_hh, ln_g, ln_b2,
        gK, gV, gXp, gH, gC, gQ, gCtx, gO, gHall, attnb);

    // ---- batched logits on tensor cores ----
    mma_gemm<<<dim3(V_ / 64, (B_ * S_) / 128), 256>>>(
        gHall, H_, lin_w, lin_b, preds, V_, H_);
}

// round 13
// speedup vs baseline: 2.2366x; 1.0081x over previous
#include <cuda_runtime.h>
#include <cuda_bf16.h>
#include <math.h>
#include <float.h>

#define B_   32
#define NF_  196
#define ENC_ 2048
#define V_   32000
#define ED_  512
#define S_   32
#define H_   1024
#define NB_  128        // persistent grid size (all co-resident on 148 SMs)

// ---------------- f32x2 packed helpers (sm_103a) -----------------------------
__device__ __forceinline__ void fma2(unsigned long long& d,
                                     unsigned long long a, unsigned long long b) {
    asm("fma.rn.f32x2 %0, %1, %2, %0;" : "+l"(d) : "l"(a), "l"(b));
}
__device__ __forceinline__ unsigned long long pack2(float lo, float hi) {
    unsigned long long r;
    asm("mov.b64 %0, {%1, %2};" : "=l"(r) : "f"(lo), "f"(hi));
    return r;
}
__device__ __forceinline__ float2 unpk2(unsigned long long v) {
    float2 r;
    asm("mov.b64 {%0, %1}, %2;" : "=f"(r.x), "=f"(r.y) : "l"(v));
    return r;
}

// ---------------- scratch ----------------------------------------------------
static constexpr size_t SZ_K    = (size_t)B_ * NF_ * H_;
static constexpr size_t OFF_K   = 0;
static constexpr size_t OFF_V   = OFF_K + SZ_K;
static constexpr size_t OFF_MEAN= OFF_V + SZ_K;
static constexpr size_t OFF_H   = OFF_MEAN + (size_t)B_ * ENC_;
static constexpr size_t OFF_C   = OFF_H   + (size_t)B_ * H_;
static constexpr size_t OFF_Q   = OFF_C   + (size_t)B_ * H_;
static constexpr size_t OFF_CTX = OFF_Q   + (size_t)B_ * H_;
static constexpr size_t OFF_O   = OFF_CTX + (size_t)B_ * H_;
static constexpr size_t OFF_SC  = OFF_O   + (size_t)B_ * H_;      // scores 32*256
static constexpr size_t OFF_EMB = OFF_SC  + (size_t)B_ * 256;
static constexpr size_t OFF_XP  = OFF_EMB + (size_t)B_ * S_ * ED_;
static constexpr size_t OFF_HALL= OFF_XP  + (size_t)B_ * S_ * 4 * H_;
static constexpr size_t OFF_AD  = OFF_HALL+ (size_t)B_ * S_ * H_;
static constexpr size_t TOTAL_F = OFF_AD  + (size_t)B_ * S_ * NF_;

__device__ float g_scratch[TOTAL_F];
__device__ unsigned g_bar_count = 0;
__device__ unsigned g_bar_gen   = 0;

// ---------------- grid-wide barrier ------------------------------------------
__device__ __forceinline__ void grid_bar() {
    __syncthreads();
    if (threadIdx.x == 0) {
        __threadfence();
        unsigned gen = *(volatile unsigned*)&g_bar_gen;
        unsigned a = atomicAdd(&g_bar_count, 1u);
        if (a == NB_ - 1) {
            atomicExch(&g_bar_count, 0u);
            __threadfence();
            atomicAdd(&g_bar_gen, 1u);
        } else {
            while (*(volatile unsigned*)&g_bar_gen == gen) __nanosleep(64);
        }
        __threadfence();
    }
    __syncthreads();
}

// ---------------- mean over N + exact gelu -----------------------------------
__global__ __launch_bounds__(256) void mean_gelu_kernel(
    const float* __restrict__ feat, float* __restrict__ outMean)
{
    int b = blockIdx.y;
    int e = blockIdx.x * 256 + threadIdx.x;
    const float* p = feat + (size_t)b * NF_ * ENC_ + e;
    float s = 0.f;
    #pragma unroll 4
    for (int n = 0; n < NF_; n++) s += p[(size_t)n * ENC_];
    s *= (1.0f / (float)NF_);
    outMean[(size_t)b * ENC_ + e] = 0.5f * s * (1.0f + erff(s * 0.70710678118654752f));
}

// ---------------- embedding gather -------------------------------------------
__global__ __launch_bounds__(256) void gather_kernel(
    const float* __restrict__ emb, const int* __restrict__ cap,
    float* __restrict__ out)
{
    int idx = blockIdx.x * 256 + threadIdx.x;
    int d  = idx & (ED_ - 1);
    int bs = idx >> 9;
    out[idx] = emb[(size_t)cap[bs] * ED_ + d];
}

// ---------------- batched GEMV for M=32 (setup h0/c0 only) -------------------
__global__ __launch_bounds__(256) void gemvM32(
    const float* __restrict__ A, const float* __restrict__ W,
    const float* __restrict__ bias, float* __restrict__ C, int ldc, int K)
{
    __shared__ float sA[32][64];
    int tid = threadIdx.x, lane = tid & 31, w = tid >> 5;
    int n = blockIdx.x * 8 + w;
    const float* Wn = W + (size_t)n * K;
    float acc[32];
    #pragma unroll
    for (int b = 0; b < 32; b++) acc[b] = 0.f;
    for (int k0 = 0; k0 < K; k0 += 64) {
        __syncthreads();
        int kk = tid & 63, bb = tid >> 6;
        #pragma unroll
        for (int i = 0; i < 8; i++)
            sA[bb + i * 4][kk] = A[(size_t)(bb + i * 4) * K + k0 + kk];
        __syncthreads();
        float w0 = Wn[k0 + lane], w1 = Wn[k0 + 32 + lane];
        #pragma unroll
        for (int b = 0; b < 32; b++)
            acc[b] += w0 * sA[b][lane] + w1 * sA[b][lane + 32];
    }
    float out = 0.f;
    #pragma unroll
    for (int b = 0; b < 32; b++) {
        float v = acc[b];
        #pragma unroll
        for (int o = 16; o; o >>= 1) v += __shfl_xor_sync(0xffffffffu, v, o);
        if (lane == b) out = v;
    }
    C[(size_t)lane * (size_t)ldc + n] = out + bias[n];
}

// ---------------- mma.sync bf16x3 GEMM (reg-staged pipeline) -----------------
// C[M][N] = A[M][K] @ W[N][K]^T + bias  (fp32 in/out; bf16 hi/lo split; fp32 acc)
// block: 256 thr = 8 warps (4M x 2N); tile 128x64; warp tile 32x32; K-chunk 32.
#define MMA16816(d, a, b) \
    asm volatile("mma.sync.aligned.m16n8k16.row.col.f32.bf16.bf16.f32 " \
        "{%0,%1,%2,%3}, {%4,%5,%6,%7}, {%8,%9}, {%0,%1,%2,%3};" \
        : "+f"((d)[0]), "+f"((d)[1]), "+f"((d)[2]), "+f"((d)[3]) \
        : "r"((a)[0]), "r"((a)[1]), "r"((a)[2]), "r"((a)[3]), \
          "r"((b)[0]), "r"((b)[1]))

__device__ __forceinline__ void cvt8v(
    float4 x0, float4 x1, unsigned* dh, unsigned* dl)
{
    unsigned h[4], l[4];
    asm("cvt.rn.bf16x2.f32 %0, %1, %2;" : "=r"(h[0]) : "f"(x0.y), "f"(x0.x));
    asm("cvt.rn.bf16x2.f32 %0, %1, %2;" : "=r"(h[1]) : "f"(x0.w), "f"(x0.z));
    asm("cvt.rn.bf16x2.f32 %0, %1, %2;" : "=r"(h[2]) : "f"(x1.y), "f"(x1.x));
    asm("cvt.rn.bf16x2.f32 %0, %1, %2;" : "=r"(h[3]) : "f"(x1.w), "f"(x1.z));
    float r0 = x0.x - __uint_as_float(h[0] << 16);
    float r1 = x0.y - __uint_as_float(h[0] & 0xffff0000u);
    float r2 = x0.z - __uint_as_float(h[1] << 16);
    float r3 = x0.w - __uint_as_float(h[1] & 0xffff0000u);
    float r4 = x1.x - __uint_as_float(h[2] << 16);
    float r5 = x1.y - __uint_as_float(h[2] & 0xffff0000u);
    float r6 = x1.z - __uint_as_float(h[3] << 16);
    float r7 = x1.w - __uint_as_float(h[3] & 0xffff0000u);
    asm("cvt.rn.bf16x2.f32 %0, %1, %2;" : "=r"(l[0]) : "f"(r1), "f"(r0));
    asm("cvt.rn.bf16x2.f32 %0, %1, %2;" : "=r"(l[1]) : "f"(r3), "f"(r2));
    asm("cvt.rn.bf16x2.f32 %0, %1, %2;" : "=r"(l[2]) : "f"(r5), "f"(r4));
    asm("cvt.rn.bf16x2.f32 %0, %1, %2;" : "=r"(l[3]) : "f"(r7), "f"(r6));
    *(uint4*)dh = make_uint4(h[0], h[1], h[2], h[3]);
    *(uint4*)dl = make_uint4(l[0], l[1], l[2], l[3]);
}

__global__ __launch_bounds__(256, 2) void mma_gemm(
    const float* __restrict__ A, int lda,
    const float* __restrict__ W,          // [N][K] row-major
    const float* __restrict__ bias,
    float* __restrict__ C, int ldc, int K)
{
    __shared__ unsigned sAh[128 * 20], sAl[128 * 20];
    __shared__ unsigned sBh[64 * 20],  sBl[64 * 20];

    int tid = threadIdx.x, lane = tid & 31, wid = tid >> 5;
    int wm = wid & 3, wn = wid >> 2;          // warp grid 4(M) x 2(N)
    int g = lane >> 2, tig = lane & 3;
    int m0 = blockIdx.y * 128, n0 = blockIdx.x * 64;

    float acc[2][4][4];
    #pragma unroll
    for (int mt = 0; mt < 2; mt++)
        #pragma unroll
        for (int nt = 0; nt < 4; nt++)
            #pragma unroll
            for (int i = 0; i < 4; i++) acc[mt][nt][i] = 0.f;

    int arow = tid >> 1, ahalf = tid & 1;     // A: row, 16-elem half
    int brow = tid >> 2, bq = tid & 3;        // B: row, 8-elem quarter
    unsigned offA = (unsigned)(arow * 20 + ahalf * 8);
    unsigned offB = (unsigned)(brow * 20 + bq * 4);

    const float* Abase = A + (size_t)(m0 + arow) * lda + ahalf * 16;
    const float* Bbase = W + (size_t)(n0 + brow) * K + bq * 8;

    float4 aS[4], bS[2];
    // prologue: load chunk 0 into registers
    aS[0] = *(const float4*)(Abase);
    aS[1] = *(const float4*)(Abase + 4);
    aS[2] = *(const float4*)(Abase + 8);
    aS[3] = *(const float4*)(Abase + 12);
    bS[0] = *(const float4*)(Bbase);
    bS[1] = *(const float4*)(Bbase + 4);

    int nchunks = K >> 5;
    for (int c = 0; c < nchunks; c++) {
        // convert staged regs -> smem
        cvt8v(aS[0], aS[1], sAh + offA,     sAl + offA);
        cvt8v(aS[2], aS[3], sAh + offA + 4, sAl + offA + 4);
        cvt8v(bS[0], bS[1], sBh + offB,     sBl + offB);
        __syncthreads();
        // prefetch next chunk into regs (LDG latency hidden by MMAs)
        if (c + 1 < nchunks) {
            const float* an = Abase + (c + 1) * 32;
            const float* bn = Bbase + (c + 1) * 32;
            aS[0] = *(const float4*)(an);
            aS[1] = *(const float4*)(an + 4);
            aS[2] = *(const float4*)(an + 8);
            aS[3] = *(const float4*)(an + 12);
            bS[0] = *(const float4*)(bn);
            bS[1] = *(const float4*)(bn + 4);
        }
        #pragma unroll
        for (int ks = 0; ks < 2; ks++) {
            unsigned ah[2][4], al[2][4], bh[4][2], bl[4][2];
            #pragma unroll
            for (int mt = 0; mt < 2; mt++) {
                int r = wm * 32 + mt * 16 + g;
                int base = r * 20 + ks * 8 + tig;
                ah[mt][0] = sAh[base];
                ah[mt][1] = sAh[base + 160];
                ah[mt][2] = sAh[base + 4];
                ah[mt][3] = sAh[base + 164];
                al[mt][0] = sAl[base];
                al[mt][1] = sAl[base + 160];
                al[mt][2] = sAl[base + 4];
                al[mt][3] = sAl[base + 164];
            }
            #pragma unroll
            for (int nt = 0; nt < 4; nt++) {
                int n = wn * 32 + nt * 8 + g;
                int base = n * 20 + ks * 8 + tig;
                bh[nt][0] = sBh[base];
                bh[nt][1] = sBh[base + 4];
                bl[nt][0] = sBl[base];
                bl[nt][1] = sBl[base + 4];
            }
            #pragma unroll
            for (int mt = 0; mt < 2; mt++)
                #pragma unroll
                for (int nt = 0; nt < 4; nt++) {
                    MMA16816(acc[mt][nt], ah[mt], bh[nt]);
                    MMA16816(acc[mt][nt], ah[mt], bl[nt]);
                    MMA16816(acc[mt][nt], al[mt], bh[nt]);
                }
        }
        __syncthreads();
    }

    #pragma unroll
    for (int mt = 0; mt < 2; mt++) {
        int row = m0 + wm * 32 + mt * 16 + g;
        #pragma unroll
        for (int nt = 0; nt < 4; nt++) {
            int col = n0 + wn * 32 + nt * 8 + 2 * tig;
            float2 bb = *(const float2*)(bias + col);
            float2 r0 = make_float2(acc[mt][nt][0] + bb.x, acc[mt][nt][1] + bb.y);
            float2 r1 = make_float2(acc[mt][nt][2] + bb.x, acc[mt][nt][3] + bb.y);
            *(float2*)(C + (size_t)row * ldc + col)       = r0;
            *(float2*)(C + (size_t)(row + 8) * ldc + col) = r1;
        }
    }
}

// ---------------- persistent recurrence kernel -------------------------------
extern __shared__ float dsm[];

__device__ __forceinline__ void gemv_direct(
    const float* __restrict__ Ag, const float* sW,
    const float* __restrict__ bias, int n0,
    const float* __restrict__ addH,
    float* __restrict__ Cg, int tid)
{
    int lane = tid & 31, w = tid >> 5;
    unsigned long long acc[32];
    #pragma unroll
    for (int p = 0; p < 32; p++) acc[p] = 0ull;

    const float* xb = Ag + (size_t)(4 * w) * H_ + 4 * lane;
    #pragma unroll
    for (int c = 0; c < 8; c++) {
        ulonglong2 xv[4];
        #pragma unroll
        for (int b = 0; b < 4; b++)
            xv[b] = *(const ulonglong2*)(xb + (size_t)b * H_ + c * 128);
        #pragma unroll
        for (int n = 0; n < 8; n++) {
            ulonglong2 wv = *(const ulonglong2*)&sW[n * H_ + c * 128 + 4 * lane];
            #pragma unroll
            for (int b = 0; b < 4; b++) {
                fma2(acc[b * 8 + n], xv[b].x, wv.x);
                fma2(acc[b * 8 + n], xv[b].y, wv.y);
            }
        }
    }
    float outv = 0.f;
    #pragma unroll
    for (int p = 0; p < 32; p++) {
        float2 v = unpk2(acc[p]);
        float s = v.x + v.y;
        #pragma unroll
        for (int o = 16; o; o >>= 1) s += __shfl_xor_sync(0xffffffffu, s, o);
        if (lane == p) outv = s;
    }
    int bg = 4 * w + (lane >> 3);
    int ng = n0 + (lane & 7);
    float r = outv + bias[ng];
    if (addH) r += addH[(size_t)bg * H_ + ng];
    Cg[(size_t)bg * H_ + ng] = r;
}

__global__ __launch_bounds__(256, 1) void recurrence_kernel(
    const float* __restrict__ q_w,  const float* __restrict__ in_b,
    const float* __restrict__ out_w,const float* __restrict__ out_b,
    const float* __restrict__ w_hh, const float* __restrict__ b_hh,
    const float* __restrict__ ln_g, const float* __restrict__ ln_b2,
    const float* __restrict__ gK,   const float* __restrict__ gV,
    const float* __restrict__ gXp,
    float* gH, float* gC, float* gQ, float* gSc,
    float* gCtx, float* gO, float* gHall, float* attnb)
{
    __shared__ float sQ[1024];
    __shared__ float sProb[224];
    __shared__ float sred[8];
    __shared__ float sbc;
    __shared__ float sG[1024];
    __shared__ float sMu[32], sRs[32];

    float* SQW  = dsm;
    float* SOW  = dsm + 8192;
    float* SWH  = dsm + 16384;
    float* SLNG = dsm + 49152;
    float* SLNB = dsm + 50176;

    int tid = threadIdx.x, lane = tid & 31, w = tid >> 5;
    int bx = blockIdx.x;
    int ab = bx >> 2, apart = bx & 3;   // attention: 4 blocks per batch

    for (int i = tid; i < 8192; i += 256) {
        SQW[i] = q_w [(size_t)bx * 8192 + i];
        SOW[i] = out_w[(size_t)bx * 8192 + i];
    }
    for (int g = 0; g < 4; g++)
        for (int i = tid; i < 8192; i += 256)
            SWH[g * 8192 + i] = w_hh[((size_t)g * H_ + bx * 8) * H_ + i];
    for (int i = tid; i < 1024; i += 256) {
        SLNG[i] = ln_g[i];
        SLNB[i] = ln_b2[i];
    }
    __syncthreads();

    for (int t = 0; t < S_; t++) {
        // ---- P0: q = h @ q_w^T + in_b[:H] ----
        gemv_direct(gH, SQW, in_b, bx * 8, nullptr, gQ, tid);
        grid_bar();

        // ---- P1a: scores (all 128 blocks; block covers 49 n of batch ab) ----
        {
            for (int i = tid; i < 1024; i += 256)
                sQ[i] = gQ[(size_t)ab * H_ + i];
            __syncthreads();
            for (int n = apart * 49 + w; n < apart * 49 + 49; n += 8) {
                const float* kp = gK + ((size_t)ab * NF_ + n) * H_;
                float s = 0.f;
                #pragma unroll
                for (int j = 0; j < 8; j++) {
                    float4 q4 = *(const float4*)&sQ[4 * lane + 128 * j];
                    float4 k4 = *(const float4*)(kp + 4 * lane + 128 * j);
                    s += q4.x*k4.x + q4.y*k4.y + q4.z*k4.z + q4.w*k4.w;
                }
                #pragma unroll
                for (int o = 16; o; o >>= 1) s += __shfl_xor_sync(0xffffffffu, s, o);
                if (lane == 0) gSc[ab * 256 + n] = s * 0.03125f;
            }
        }
        grid_bar();

        // ---- P1b: softmax (redundant x4) + ctx (block covers 256 h) ----
        {
            float v = (tid < NF_) ? gSc[ab * 256 + tid] : -FLT_MAX;
            float m = v;
            #pragma unroll
            for (int o = 16; o; o >>= 1) m = fmaxf(m, __shfl_xor_sync(0xffffffffu, m, o));
            if (lane == 0) sred[w] = m;
            __syncthreads();
            if (tid == 0) {
                float mm = sred[0];
                #pragma unroll
                for (int i = 1; i < 8; i++) mm = fmaxf(mm, sred[i]);
                sbc = mm;
            }
            __syncthreads();
            float e = (tid < NF_) ? expf(v - sbc) : 0.f;
            float s2 = e;
            #pragma unroll
            for (int o = 16; o; o >>= 1) s2 += __shfl_xor_sync(0xffffffffu, s2, o);
            if (lane == 0) sred[w] = s2;
            __syncthreads();
            if (tid == 0) {
                float ss = 0.f;
                #pragma unroll
                for (int i = 0; i < 8; i++) ss += sred[i];
                sbc = ss;
            }
            __syncthreads();
            float p = e / sbc;
            if (tid < NF_) {
                sProb[tid] = p;
                if (apart == 0)
                    attnb[((size_t)ab * S_ + t) * NF_ + tid] = p;
            }
            __syncthreads();
            // ctx: h = apart*256 + tid (one scalar col per thread)
            {
                int h = apart * 256 + tid;
                const float* vb = gV + (size_t)ab * NF_ * H_ + h;
                float a = 0.f;
                #pragma unroll 1
                for (int n0b = 0; n0b < 192; n0b += 8) {
                    float vv[8];
                    #pragma unroll
                    for (int j = 0; j < 8; j++)
                        vv[j] = vb[(size_t)(n0b + j) * H_];
                    #pragma unroll
                    for (int j = 0; j < 8; j++)
                        a += sProb[n0b + j] * vv[j];
                }
                #pragma unroll
                for (int j = 0; j < 4; j++)
                    a += sProb[192 + j] * vb[(size_t)(192 + j) * H_];
                gCtx[(size_t)ab * H_ + h] = a;
            }
        }
        grid_bar();

        // ---- P3: x = h + ctx @ out_w^T + out_b ----
        gemv_direct(gCtx, SOW, out_b, bx * 8, gH, gO, tid);
        grid_bar();

        // ---- P5: LN (on the fly) + gates + LSTM ----
        {
            {
                int b = tid >> 3, sl = tid & 7;
                const float* xb = gO + (size_t)b * H_ + sl * 4;
                float s = 0.f, s2 = 0.f;
                #pragma unroll 8
                for (int i = 0; i < 32; i++) {
                    float4 v = *(const float4*)(xb + i * 32);
                    s  += v.x + v.y + v.z + v.w;
                    s2 += v.x*v.x + v.y*v.y + v.z*v.z + v.w*v.w;
                }
                #pragma unroll
                for (int o2 = 1; o2 < 8; o2 <<= 1) {
                    s  += __shfl_xor_sync(0xffffffffu, s,  o2);
                    s2 += __shfl_xor_sync(0xffffffffu, s2, o2);
                }
                if (sl == 0) {
                    float mu = s * (1.0f / H_);
                    float var = s2 * (1.0f / H_) - mu * mu;
                    sMu[b] = mu;
                    sRs[b] = rsqrtf(var + 1e-5f);
                }
            }
            __syncthreads();

            const float* xb = gO + (size_t)(4 * w) * H_ + 4 * lane;
            float muv[4], rsv[4];
            #pragma unroll
            for (int b = 0; b < 4; b++) {
                muv[b] = sMu[4 * w + b];
                rsv[b] = sRs[4 * w + b];
            }

            #pragma unroll 1
            for (int p2 = 0; p2 < 2; p2++) {
                int g0 = 2 * p2, g1 = 2 * p2 + 1;
                const float* W0 = SWH + (size_t)g0 * 8192;
                const float* W1 = SWH + (size_t)g1 * 8192;
                unsigned long long aA[32], aB[32];
                #pragma unroll
                for (int p = 0; p < 32; p++) { aA[p] = 0ull; aB[p] = 0ull; }

                #pragma unroll
                for (int c = 0; c < 8; c++) {
                    float4 g4 = *(const float4*)&SLNG[c * 128 + 4 * lane];
                    float4 b4 = *(const float4*)&SLNB[c * 128 + 4 * lane];
                    ulonglong2 xn[4];
                    #pragma unroll
                    for (int b = 0; b < 4; b++) {
                        float4 x = *(const float4*)(xb + (size_t)b * H_ + c * 128);
                        float mu = muv[b], rs = rsv[b];
                        float4 r;
                        r.x = (x.x - mu) * rs * g4.x + b4.x;
                        r.y = (x.y - mu) * rs * g4.y + b4.y;
                        r.z = (x.z - mu) * rs * g4.z + b4.z;
                        r.w = (x.w - mu) * rs * g4.w + b4.w;
                        xn[b].x = pack2(r.x, r.y);
                        xn[b].y = pack2(r.z, r.w);
                    }
                    #pragma unroll
                    for (int n = 0; n < 8; n++) {
                        ulonglong2 w0 = *(const ulonglong2*)&W0[n * H_ + c * 128 + 4 * lane];
                        ulonglong2 w1 = *(const ulonglong2*)&W1[n * H_ + c * 128 + 4 * lane];
                        #pragma unroll
                        for (int b = 0; b < 4; b++) {
                            fma2(aA[b * 8 + n], xn[b].x, w0.x);
                            fma2(aA[b * 8 + n], xn[b].y, w0.y);
                            fma2(aB[b * 8 + n], xn[b].x, w1.x);
                            fma2(aB[b * 8 + n], xn[b].y, w1.y);
                        }
                    }
                }
                float oA = 0.f, oB = 0.f;
                #pragma unroll
                for (int p = 0; p < 32; p++) {
                    float2 va = unpk2(aA[p]);
                    float2 vb = unpk2(aB[p]);
                    float sa = va.x + va.y, sb2 = vb.x + vb.y;
                    #pragma unroll
                    for (int o = 16; o; o >>= 1) {
                        sa  += __shfl_xor_sync(0xffffffffu, sa,  o);
                        sb2 += __shfl_xor_sync(0xffffffffu, sb2, o);
                    }
                    if (lane == p) { oA = sa; oB = sb2; }
                }
                int bg = 4 * w + (lane >> 3);
                int c  = lane & 7;
                int nA = g0 * H_ + bx * 8 + c;
                int nB = g1 * H_ + bx * 8 + c;
                size_t xrow = ((size_t)bg * S_ + t) * (4 * H_);
                oA += b_hh[nA] + gXp[xrow + nA];
                oB += b_hh[nB] + gXp[xrow + nB];
                sG[g0 * 256 + c * 32 + bg] = oA;
                sG[g1 * 256 + c * 32 + bg] = oB;
            }
            __syncthreads();
            int b = tid & 31, jj = tid >> 5;
            int j2 = bx * 8 + jj;
            float ii = sG[0 * 256 + jj * 32 + b];
            float ff = sG[1 * 256 + jj * 32 + b];
            float gg = sG[2 * 256 + jj * 32 + b];
            float oo = sG[3 * 256 + jj * 32 + b];
            float si = 1.f / (1.f + expf(-ii));
            float sf = 1.f / (1.f + expf(-ff));
            float so = 1.f / (1.f + expf(-oo));
            float cn = sf * gC[b * H_ + j2] + si * tanhf(gg);
            float hn = so * tanhf(cn);
            gC[b * H_ + j2] = cn;
            gH[b * H_ + j2] = hn;
            gHall[((size_t)b * S_ + t) * H_ + j2] = hn;
        }
        grid_bar();
    }
}

// ---------------- orchestration ----------------------------------------------
extern "C" void kernel_launch(void* const* d_in, const int* in_sizes, int n_in,
                              void* d_out, int out_size)
{
    const float* features = (const float*)d_in[0];
    const int*   captions = (const int*)  d_in[1];
    const float* emb      = (const float*)d_in[2];
    const float* q_w      = (const float*)d_in[3];
    const float* k_w      = (const float*)d_in[4];
    const float* v_w      = (const float*)d_in[5];
    const float* in_b     = (const float*)d_in[6];
    const float* out_w    = (const float*)d_in[7];
    const float* out_b    = (const float*)d_in[8];
    const float* h0_w     = (const float*)d_in[9];
    const float* h0_b     = (const float*)d_in[10];
    const float* c0_w     = (const float*)d_in[11];
    const float* c0_b     = (const float*)d_in[12];
    const float* w_ih     = (const float*)d_in[13];
    const float* b_ih     = (const float*)d_in[14];
    const float* w_hh     = (const float*)d_in[15];
    const float* b_hh     = (const float*)d_in[16];
    const float* ln_g     = (const float*)d_in[17];
    const float* ln_b2    = (const float*)d_in[18];
    const float* lin_w    = (const float*)d_in[19];
    const float* lin_b    = (const float*)d_in[20];

    float* sc = nullptr;
    cudaGetSymbolAddress((void**)&sc, g_scratch);
    float* gK    = sc + OFF_K;
    float* gV    = sc + OFF_V;
    float* gMean = sc + OFF_MEAN;
    float* gH    = sc + OFF_H;
    float* gC    = sc + OFF_C;
    float* gQ    = sc + OFF_Q;
    float* gCtx  = sc + OFF_CTX;
    float* gO    = sc + OFF_O;
    float* gSc   = sc + OFF_SC;
    float* gEmb  = sc + OFF_EMB;
    float* gXp   = sc + OFF_XP;
    float* gHall = sc + OFF_HALL;
    float* gAd   = sc + OFF_AD;

    float* out   = (float*)d_out;
    float* preds = out;
    const size_t PRED = (size_t)B_ * S_ * V_;
    bool wa = ((size_t)out_size >= PRED + (size_t)B_ * S_ * NF_);
    float* attnb = wa ? (out + PRED) : gAd;

    const int REC_SMEM = 51200 * 4;   // 200 KB for recurrence
    cudaFuncSetAttribute(recurrence_kernel,
                         cudaFuncAttributeMaxDynamicSharedMemorySize, REC_SMEM);

    // ---- setup (hoisted) ----
    mean_gelu_kernel<<<dim3(ENC_ / 256, B_), 256>>>(features, gMean);
    gemvM32<<<H_ / 8, 256>>>(gMean, h0_w, h0_b, gH, H_, ENC_);
    gemvM32<<<H_ / 8, 256>>>(gMean, c0_w, c0_b, gC, H_, ENC_);
    mma_gemm<<<dim3(H_ / 64, (B_ * NF_) / 128), 256>>>(
        features, ENC_, k_w, in_b + H_,     gK, H_, ENC_);
    mma_gemm<<<dim3(H_ / 64, (B_ * NF_) / 128), 256>>>(
        features, ENC_, v_w, in_b + 2 * H_, gV, H_, ENC_);
    gather_kernel<<<(B_ * S_ * ED_) / 256, 256>>>(emb, captions, gEmb);
    mma_gemm<<<dim3((4 * H_) / 64, (B_ * S_) / 128), 256>>>(
        gEmb, ED_, w_ih, b_ih, gXp, 4 * H_, ED_);

    // ---- recurrence in one persistent kernel ----
    recurrence_kernel<<<NB_, 256, REC_SMEM>>>(
        q_w, in_b, out_w, out_b, w_hh, b_hh, ln_g, ln_b2,
        gK, gV, gXp, gH, gC, gQ, gSc, gCtx, gO, gHall, attnb);

    // ---- batched logits on tensor cores ----
    mma_gemm<<<dim3(V_ / 64, (B_ * S_) / 128), 256>>>(
        gHall, H_, lin_w, lin_b, preds, V_, H_);
}

// round 14
// speedup vs baseline: 2.3999x; 1.0730x over previous
#include <cuda_runtime.h>
#include <cuda_bf16.h>
#include <math.h>
#include <float.h>

#define B_   32
#define NF_  196
#define ENC_ 2048
#define V_   32000
#define ED_  512
#define S_   32
#define H_   1024
#define NB_  128        // persistent grid size (all co-resident on 148 SMs)

// ---------------- f32x2 packed helpers (sm_103a) -----------------------------
__device__ __forceinline__ void fma2(unsigned long long& d,
                                     unsigned long long a, unsigned long long b) {
    asm("fma.rn.f32x2 %0, %1, %2, %0;" : "+l"(d) : "l"(a), "l"(b));
}
__device__ __forceinline__ unsigned long long pack2(float lo, float hi) {
    unsigned long long r;
    asm("mov.b64 %0, {%1, %2};" : "=l"(r) : "f"(lo), "f"(hi));
    return r;
}
__device__ __forceinline__ float2 unpk2(unsigned long long v) {
    float2 r;
    asm("mov.b64 {%0, %1}, %2;" : "=f"(r.x), "=f"(r.y) : "l"(v));
    return r;
}
__device__ __forceinline__ unsigned su32(const void* p) {
    return (unsigned)__cvta_generic_to_shared(p);
}
#define CP16(dst, src) \
    asm volatile("cp.async.cg.shared.global [%0], [%1], 16;" :: "r"(dst), "l"(src))
#define CPCOMMIT() asm volatile("cp.async.commit_group;")
#define CPWAIT(n)  asm volatile("cp.async.wait_group %0;" :: "n"(n))

// ---------------- scratch ----------------------------------------------------
static constexpr size_t SZ_K    = (size_t)B_ * NF_ * H_;
static constexpr size_t OFF_K   = 0;
static constexpr size_t OFF_V   = OFF_K + SZ_K;
static constexpr size_t OFF_MEAN= OFF_V + SZ_K;
static constexpr size_t OFF_H   = OFF_MEAN + (size_t)B_ * ENC_;
static constexpr size_t OFF_C   = OFF_H   + (size_t)B_ * H_;
static constexpr size_t OFF_Q   = OFF_C   + (size_t)B_ * H_;
static constexpr size_t OFF_CTX = OFF_Q   + (size_t)B_ * H_;
static constexpr size_t OFF_O   = OFF_CTX + (size_t)B_ * H_;
static constexpr size_t OFF_SC  = OFF_O   + (size_t)B_ * H_;
static constexpr size_t OFF_XP  = OFF_SC  + (size_t)B_ * 256;
static constexpr size_t OFF_AD  = OFF_XP  + (size_t)B_ * S_ * 4 * H_;
// bf16 hi/lo regions (sizes in floats = u16count/2; all multiples of 4)
static constexpr size_t OFF_FH  = OFF_AD  + (size_t)B_ * S_ * NF_;
static constexpr size_t SZ_F2   = (size_t)B_ * NF_ * ENC_ / 2;
static constexpr size_t OFF_FL  = OFF_FH  + SZ_F2;
static constexpr size_t OFF_KWH = OFF_FL  + SZ_F2;
static constexpr size_t SZ_KW2  = (size_t)H_ * ENC_ / 2;
static constexpr size_t OFF_KWL = OFF_KWH + SZ_KW2;
static constexpr size_t OFF_VWH = OFF_KWL + SZ_KW2;
static constexpr size_t OFF_VWL = OFF_VWH + SZ_KW2;
static constexpr size_t OFF_WIH = OFF_VWL + SZ_KW2;
static constexpr size_t SZ_WI2  = (size_t)4 * H_ * ED_ / 2;
static constexpr size_t OFF_WIL = OFF_WIH + SZ_WI2;
static constexpr size_t OFF_LWH = OFF_WIL + SZ_WI2;
static constexpr size_t SZ_LW2  = (size_t)V_ * H_ / 2;
static constexpr size_t OFF_LWL = OFF_LWH + SZ_LW2;
static constexpr size_t OFF_EBH = OFF_LWL + SZ_LW2;
static constexpr size_t SZ_EB2  = (size_t)B_ * S_ * ED_ / 2;
static constexpr size_t OFF_EBL = OFF_EBH + SZ_EB2;
static constexpr size_t OFF_HLH = OFF_EBL + SZ_EB2;
static constexpr size_t SZ_HL2  = (size_t)B_ * S_ * H_ / 2;
static constexpr size_t OFF_HLL = OFF_HLH + SZ_HL2;
static constexpr size_t TOTAL_F = OFF_HLL + SZ_HL2;

__device__ float g_scratch[TOTAL_F];
__device__ unsigned g_bar_count = 0;
__device__ unsigned g_bar_gen   = 0;

// ---------------- grid-wide barrier ------------------------------------------
__device__ __forceinline__ void grid_bar() {
    __syncthreads();
    if (threadIdx.x == 0) {
        __threadfence();
        unsigned gen = *(volatile unsigned*)&g_bar_gen;
        unsigned a = atomicAdd(&g_bar_count, 1u);
        if (a == NB_ - 1) {
            atomicExch(&g_bar_count, 0u);
            __threadfence();
            atomicAdd(&g_bar_gen, 1u);
        } else {
            while (*(volatile unsigned*)&g_bar_gen == gen) __nanosleep(64);
        }
        __threadfence();
    }
    __syncthreads();
}

// ---------------- bf16 hi/lo convert core ------------------------------------
__device__ __forceinline__ void cvt8v(
    float4 x0, float4 x1, unsigned* dh, unsigned* dl)
{
    unsigned h[4], l[4];
    asm("cvt.rn.bf16x2.f32 %0, %1, %2;" : "=r"(h[0]) : "f"(x0.y), "f"(x0.x));
    asm("cvt.rn.bf16x2.f32 %0, %1, %2;" : "=r"(h[1]) : "f"(x0.w), "f"(x0.z));
    asm("cvt.rn.bf16x2.f32 %0, %1, %2;" : "=r"(h[2]) : "f"(x1.y), "f"(x1.x));
    asm("cvt.rn.bf16x2.f32 %0, %1, %2;" : "=r"(h[3]) : "f"(x1.w), "f"(x1.z));
    float r0 = x0.x - __uint_as_float(h[0] << 16);
    float r1 = x0.y - __uint_as_float(h[0] & 0xffff0000u);
    float r2 = x0.z - __uint_as_float(h[1] << 16);
    float r3 = x0.w - __uint_as_float(h[1] & 0xffff0000u);
    float r4 = x1.x - __uint_as_float(h[2] << 16);
    float r5 = x1.y - __uint_as_float(h[2] & 0xffff0000u);
    float r6 = x1.z - __uint_as_float(h[3] << 16);
    float r7 = x1.w - __uint_as_float(h[3] & 0xffff0000u);
    asm("cvt.rn.bf16x2.f32 %0, %1, %2;" : "=r"(l[0]) : "f"(r1), "f"(r0));
    asm("cvt.rn.bf16x2.f32 %0, %1, %2;" : "=r"(l[1]) : "f"(r3), "f"(r2));
    asm("cvt.rn.bf16x2.f32 %0, %1, %2;" : "=r"(l[2]) : "f"(r5), "f"(r4));
    asm("cvt.rn.bf16x2.f32 %0, %1, %2;" : "=r"(l[3]) : "f"(r7), "f"(r6));
    *(uint4*)dh = make_uint4(h[0], h[1], h[2], h[3]);
    *(uint4*)dl = make_uint4(l[0], l[1], l[2], l[3]);
}

// ---------------- elementwise split: fp32 -> bf16 hi/lo ----------------------
__global__ __launch_bounds__(256) void split_bf16(
    const float* __restrict__ in,
    unsigned short* __restrict__ hi, unsigned short* __restrict__ lo)
{
    size_t i = ((size_t)blockIdx.x * 256 + threadIdx.x) * 8;
    float4 x0 = *(const float4*)(in + i);
    float4 x1 = *(const float4*)(in + i + 4);
    cvt8v(x0, x1, (unsigned*)(hi + i), (unsigned*)(lo + i));
}

// ---------------- mean over N + exact gelu -----------------------------------
__global__ __launch_bounds__(256) void mean_gelu_kernel(
    const float* __restrict__ feat, float* __restrict__ outMean)
{
    int b = blockIdx.y;
    int e = blockIdx.x * 256 + threadIdx.x;
    const float* p = feat + (size_t)b * NF_ * ENC_ + e;
    float s = 0.f;
    #pragma unroll 4
    for (int n = 0; n < NF_; n++) s += p[(size_t)n * ENC_];
    s *= (1.0f / (float)NF_);
    outMean[(size_t)b * ENC_ + e] = 0.5f * s * (1.0f + erff(s * 0.70710678118654752f));
}

// ---------------- embedding gather (emits bf16 hi/lo) ------------------------
__global__ __launch_bounds__(256) void gather_kernel(
    const float* __restrict__ emb, const int* __restrict__ cap,
    unsigned short* __restrict__ outH, unsigned short* __restrict__ outL)
{
    int idx = blockIdx.x * 256 + threadIdx.x;
    int d  = idx & (ED_ - 1);
    int bs = idx >> 9;
    float v = emb[(size_t)cap[bs] * ED_ + d];
    __nv_bfloat16 hb = __float2bfloat16(v);
    float hf = __bfloat162float(hb);
    __nv_bfloat16 lb = __float2bfloat16(v - hf);
    outH[idx] = *(unsigned short*)&hb;
    outL[idx] = *(unsigned short*)&lb;
}

// ---------------- batched GEMV for M=32 (setup h0/c0 only) -------------------
__global__ __launch_bounds__(256) void gemvM32(
    const float* __restrict__ A, const float* __restrict__ W,
    const float* __restrict__ bias, float* __restrict__ C, int ldc, int K)
{
    __shared__ float sA[32][64];
    int tid = threadIdx.x, lane = tid & 31, w = tid >> 5;
    int n = blockIdx.x * 8 + w;
    const float* Wn = W + (size_t)n * K;
    float acc[32];
    #pragma unroll
    for (int b = 0; b < 32; b++) acc[b] = 0.f;
    for (int k0 = 0; k0 < K; k0 += 64) {
        __syncthreads();
        int kk = tid & 63, bb = tid >> 6;
        #pragma unroll
        for (int i = 0; i < 8; i++)
            sA[bb + i * 4][kk] = A[(size_t)(bb + i * 4) * K + k0 + kk];
        __syncthreads();
        float w0 = Wn[k0 + lane], w1 = Wn[k0 + 32 + lane];
        #pragma unroll
        for (int b = 0; b < 32; b++)
            acc[b] += w0 * sA[b][lane] + w1 * sA[b][lane + 32];
    }
    float out = 0.f;
    #pragma unroll
    for (int b = 0; b < 32; b++) {
        float v = acc[b];
        #pragma unroll
        for (int o = 16; o; o >>= 1) v += __shfl_xor_sync(0xffffffffu, v, o);
        if (lane == b) out = v;
    }
    C[(size_t)lane * (size_t)ldc + n] = out + bias[n];
}

// ---------------- mma.sync bf16x3 GEMM, pre-split inputs, cp.async pipeline --
// C[M][N] = (Ah+Al)[M][K] @ (Bh+Bl)[N][K]^T + bias  (fp32 accum, al*bl dropped)
// block: 256 thr = 8 warps (4M x 2N); tile 128x64; K-chunk 32 bf16.
#define MMA16816(d, a, b) \
    asm volatile("mma.sync.aligned.m16n8k16.row.col.f32.bf16.bf16.f32 " \
        "{%0,%1,%2,%3}, {%4,%5,%6,%7}, {%8,%9}, {%0,%1,%2,%3};" \
        : "+f"((d)[0]), "+f"((d)[1]), "+f"((d)[2]), "+f"((d)[3]) \
        : "r"((a)[0]), "r"((a)[1]), "r"((a)[2]), "r"((a)[3]), \
          "r"((b)[0]), "r"((b)[1]))

extern __shared__ float dsm[];

// dynamic smem layout (u32 idx): sAh[2][2560] sAl[2][2560] sBh[2][1280] sBl[2][1280]
#define SM_AH(buf) ((buf) * 2560)
#define SM_AL(buf) (5120 + (buf) * 2560)
#define SM_BH(buf) (10240 + (buf) * 1280)
#define SM_BL(buf) (12800 + (buf) * 1280)
#define MMA_SMEM_BYTES (15360 * 4)

__global__ __launch_bounds__(256) void mma_gemm_bf16(
    const unsigned short* __restrict__ Ah, const unsigned short* __restrict__ Al,
    int lda,
    const unsigned short* __restrict__ Bh, const unsigned short* __restrict__ Bl,
    const float* __restrict__ bias,
    float* __restrict__ C, int ldc, int K)
{
    unsigned* smu = (unsigned*)dsm;
    unsigned smb = su32(smu);

    int tid = threadIdx.x, lane = tid & 31, wid = tid >> 5;
    int wm = wid & 3, wn = wid >> 2;
    int g = lane >> 2, tig = lane & 3;
    int m0 = blockIdx.y * 128, n0 = blockIdx.x * 64;

    float acc[2][4][4];
    #pragma unroll
    for (int mt = 0; mt < 2; mt++)
        #pragma unroll
        for (int nt = 0; nt < 4; nt++)
            #pragma unroll
            for (int i = 0; i < 4; i++) acc[mt][nt][i] = 0.f;

    // cp.async coords: A rows 128 x 16 b32 (4 chunks/row), 2 chunks/thread
    int arow = tid >> 1, aq2 = (tid & 1) * 2;       // quads aq2, aq2+1
    int brow = tid >> 2, bq = tid & 3;              // 1 chunk/thread

    const unsigned short* Ah0 = Ah + (size_t)(m0 + arow) * lda;
    const unsigned short* Al0 = Al + (size_t)(m0 + arow) * lda;
    const unsigned short* Bh0 = Bh + (size_t)(n0 + brow) * K;
    const unsigned short* Bl0 = Bl + (size_t)(n0 + brow) * K;

    auto load_tile = [&](int c, int buf) {
        int kb = c * 32;
        unsigned da = smb + (SM_AH(buf) + arow * 20 + aq2 * 4) * 4;
        unsigned dal = smb + (SM_AL(buf) + arow * 20 + aq2 * 4) * 4;
        const unsigned short* sa = Ah0 + kb + aq2 * 8;
        const unsigned short* sal = Al0 + kb + aq2 * 8;
        CP16(da, sa);
        CP16(da + 16, sa + 8);
        CP16(dal, sal);
        CP16(dal + 16, sal + 8);
        CP16(smb + (SM_BH(buf) + brow * 20 + bq * 4) * 4, Bh0 + kb + bq * 8);
        CP16(smb + (SM_BL(buf) + brow * 20 + bq * 4) * 4, Bl0 + kb + bq * 8);
    };

    int nchunks = K >> 5;
    load_tile(0, 0);
    CPCOMMIT();

    int buf = 0;
    for (int c = 0; c < nchunks; c++) {
        if (c + 1 < nchunks) {
            load_tile(c + 1, buf ^ 1);
            CPCOMMIT();
            CPWAIT(1);
        } else {
            CPWAIT(0);
        }
        __syncthreads();
        const unsigned* pAh = smu + SM_AH(buf);
        const unsigned* pAl = smu + SM_AL(buf);
        const unsigned* pBh = smu + SM_BH(buf);
        const unsigned* pBl = smu + SM_BL(buf);
        #pragma unroll
        for (int ks = 0; ks < 2; ks++) {
            unsigned ah[2][4], al[2][4], bh[4][2], bl[4][2];
            #pragma unroll
            for (int mt = 0; mt < 2; mt++) {
                int r = wm * 32 + mt * 16 + g;
                int base = r * 20 + ks * 8 + tig;
                ah[mt][0] = pAh[base];
                ah[mt][1] = pAh[base + 160];
                ah[mt][2] = pAh[base + 4];
                ah[mt][3] = pAh[base + 164];
                al[mt][0] = pAl[base];
                al[mt][1] = pAl[base + 160];
                al[mt][2] = pAl[base + 4];
                al[mt][3] = pAl[base + 164];
            }
            #pragma unroll
            for (int nt = 0; nt < 4; nt++) {
                int n = wn * 32 + nt * 8 + g;
                int base = n * 20 + ks * 8 + tig;
                bh[nt][0] = pBh[base];
                bh[nt][1] = pBh[base + 4];
                bl[nt][0] = pBl[base];
                bl[nt][1] = pBl[base + 4];
            }
            #pragma unroll
            for (int mt = 0; mt < 2; mt++)
                #pragma unroll
                for (int nt = 0; nt < 4; nt++) {
                    MMA16816(acc[mt][nt], ah[mt], bh[nt]);
                    MMA16816(acc[mt][nt], ah[mt], bl[nt]);
                    MMA16816(acc[mt][nt], al[mt], bh[nt]);
                }
        }
        __syncthreads();
        buf ^= 1;
    }

    #pragma unroll
    for (int mt = 0; mt < 2; mt++) {
        int row = m0 + wm * 32 + mt * 16 + g;
        #pragma unroll
        for (int nt = 0; nt < 4; nt++) {
            int col = n0 + wn * 32 + nt * 8 + 2 * tig;
            float2 bb = *(const float2*)(bias + col);
            float2 r0 = make_float2(acc[mt][nt][0] + bb.x, acc[mt][nt][1] + bb.y);
            float2 r1 = make_float2(acc[mt][nt][2] + bb.x, acc[mt][nt][3] + bb.y);
            *(float2*)(C + (size_t)row * ldc + col)       = r0;
            *(float2*)(C + (size_t)(row + 8) * ldc + col) = r1;
        }
    }
}

// ---------------- persistent recurrence kernel -------------------------------
__device__ __forceinline__ void gemv_direct(
    const float* __restrict__ Ag, const float* sW,
    const float* __restrict__ bias, int n0,
    const float* __restrict__ addH,
    float* __restrict__ Cg, int tid)
{
    int lane = tid & 31, w = tid >> 5;
    unsigned long long acc[32];
    #pragma unroll
    for (int p = 0; p < 32; p++) acc[p] = 0ull;

    const float* xb = Ag + (size_t)(4 * w) * H_ + 4 * lane;
    #pragma unroll
    for (int c = 0; c < 8; c++) {
        ulonglong2 xv[4];
        #pragma unroll
        for (int b = 0; b < 4; b++)
            xv[b] = *(const ulonglong2*)(xb + (size_t)b * H_ + c * 128);
        #pragma unroll
        for (int n = 0; n < 8; n++) {
            ulonglong2 wv = *(const ulonglong2*)&sW[n * H_ + c * 128 + 4 * lane];
            #pragma unroll
            for (int b = 0; b < 4; b++) {
                fma2(acc[b * 8 + n], xv[b].x, wv.x);
                fma2(acc[b * 8 + n], xv[b].y, wv.y);
            }
        }
    }
    float outv = 0.f;
    #pragma unroll
    for (int p = 0; p < 32; p++) {
        float2 v = unpk2(acc[p]);
        float s = v.x + v.y;
        #pragma unroll
        for (int o = 16; o; o >>= 1) s += __shfl_xor_sync(0xffffffffu, s, o);
        if (lane == p) outv = s;
    }
    int bg = 4 * w + (lane >> 3);
    int ng = n0 + (lane & 7);
    float r = outv + bias[ng];
    if (addH) r += addH[(size_t)bg * H_ + ng];
    Cg[(size_t)bg * H_ + ng] = r;
}

__global__ __launch_bounds__(256, 1) void recurrence_kernel(
    const float* __restrict__ q_w,  const float* __restrict__ in_b,
    const float* __restrict__ out_w,const float* __restrict__ out_b,
    const float* __restrict__ w_hh, const float* __restrict__ b_hh,
    const float* __restrict__ ln_g, const float* __restrict__ ln_b2,
    const float* __restrict__ gK,   const float* __restrict__ gV,
    const float* __restrict__ gXp,
    float* gH, float* gC, float* gQ, float* gSc,
    float* gCtx, float* gO,
    unsigned short* gHallH, unsigned short* gHallL, float* attnb)
{
    __shared__ float sQ[1024];
    __shared__ float sProb[224];
    __shared__ float sred[8];
    __shared__ float sbc;
    __shared__ float sG[1024];
    __shared__ float sMu[32], sRs[32];

    float* SQW  = dsm;
    float* SOW  = dsm + 8192;
    float* SWH  = dsm + 16384;
    float* SLNG = dsm + 49152;
    float* SLNB = dsm + 50176;

    int tid = threadIdx.x, lane = tid & 31, w = tid >> 5;
    int bx = blockIdx.x;
    int ab = bx >> 2, apart = bx & 3;   // attention: 4 blocks per batch

    for (int i = tid; i < 8192; i += 256) {
        SQW[i] = q_w [(size_t)bx * 8192 + i];
        SOW[i] = out_w[(size_t)bx * 8192 + i];
    }
    for (int g = 0; g < 4; g++)
        for (int i = tid; i < 8192; i += 256)
            SWH[g * 8192 + i] = w_hh[((size_t)g * H_ + bx * 8) * H_ + i];
    for (int i = tid; i < 1024; i += 256) {
        SLNG[i] = ln_g[i];
        SLNB[i] = ln_b2[i];
    }
    __syncthreads();

    for (int t = 0; t < S_; t++) {
        // ---- P0: q = h @ q_w^T + in_b[:H] ----
        gemv_direct(gH, SQW, in_b, bx * 8, nullptr, gQ, tid);
        grid_bar();

        // ---- P1a: scores (block covers 49 n of batch ab) ----
        {
            for (int i = tid; i < 1024; i += 256)
                sQ[i] = gQ[(size_t)ab * H_ + i];
            __syncthreads();
            for (int n = apart * 49 + w; n < apart * 49 + 49; n += 8) {
                const float* kp = gK + ((size_t)ab * NF_ + n) * H_;
                float s = 0.f;
                #pragma unroll
                for (int j = 0; j < 8; j++) {
                    float4 q4 = *(const float4*)&sQ[4 * lane + 128 * j];
                    float4 k4 = *(const float4*)(kp + 4 * lane + 128 * j);
                    s += q4.x*k4.x + q4.y*k4.y + q4.z*k4.z + q4.w*k4.w;
                }
                #pragma unroll
                for (int o = 16; o; o >>= 1) s += __shfl_xor_sync(0xffffffffu, s, o);
                if (lane == 0) gSc[ab * 256 + n] = s * 0.03125f;
            }
        }
        grid_bar();

        // ---- P1b: softmax (redundant x4) + ctx (block covers 256 h) ----
        {
            float v = (tid < NF_) ? gSc[ab * 256 + tid] : -FLT_MAX;
            float m = v;
            #pragma unroll
            for (int o = 16; o; o >>= 1) m = fmaxf(m, __shfl_xor_sync(0xffffffffu, m, o));
            if (lane == 0) sred[w] = m;
            __syncthreads();
            if (tid == 0) {
                float mm = sred[0];
                #pragma unroll
                for (int i = 1; i < 8; i++) mm = fmaxf(mm, sred[i]);
                sbc = mm;
            }
            __syncthreads();
            float e = (tid < NF_) ? expf(v - sbc) : 0.f;
            float s2 = e;
            #pragma unroll
            for (int o = 16; o; o >>= 1) s2 += __shfl_xor_sync(0xffffffffu, s2, o);
            if (lane == 0) sred[w] = s2;
            __syncthreads();
            if (tid == 0) {
                float ss = 0.f;
                #pragma unroll
                for (int i = 0; i < 8; i++) ss += sred[i];
                sbc = ss;
            }
            __syncthreads();
            float p = e / sbc;
            if (tid < NF_) {
                sProb[tid] = p;
                if (apart == 0)
                    attnb[((size_t)ab * S_ + t) * NF_ + tid] = p;
            }
            __syncthreads();
            {
                int h = apart * 256 + tid;
                const float* vb = gV + (size_t)ab * NF_ * H_ + h;
                float a = 0.f;
                #pragma unroll 1
                for (int n0b = 0; n0b < 192; n0b += 8) {
                    float vv[8];
                    #pragma unroll
                    for (int j = 0; j < 8; j++)
                        vv[j] = vb[(size_t)(n0b + j) * H_];
                    #pragma unroll
                    for (int j = 0; j < 8; j++)
                        a += sProb[n0b + j] * vv[j];
                }
                #pragma unroll
                for (int j = 0; j < 4; j++)
                    a += sProb[192 + j] * vb[(size_t)(192 + j) * H_];
                gCtx[(size_t)ab * H_ + h] = a;
            }
        }
        grid_bar();

        // ---- P3: x = h + ctx @ out_w^T + out_b ----
        gemv_direct(gCtx, SOW, out_b, bx * 8, gH, gO, tid);
        grid_bar();

        // ---- P5: LN (on the fly) + gates + LSTM ----
        {
            {
                int b = tid >> 3, sl = tid & 7;
                const float* xb = gO + (size_t)b * H_ + sl * 4;
                float s = 0.f, s2 = 0.f;
                #pragma unroll 8
                for (int i = 0; i < 32; i++) {
                    float4 v = *(const float4*)(xb + i * 32);
                    s  += v.x + v.y + v.z + v.w;
                    s2 += v.x*v.x + v.y*v.y + v.z*v.z + v.w*v.w;
                }
                #pragma unroll
                for (int o2 = 1; o2 < 8; o2 <<= 1) {
                    s  += __shfl_xor_sync(0xffffffffu, s,  o2);
                    s2 += __shfl_xor_sync(0xffffffffu, s2, o2);
                }
                if (sl == 0) {
                    float mu = s * (1.0f / H_);
                    float var = s2 * (1.0f / H_) - mu * mu;
                    sMu[b] = mu;
                    sRs[b] = rsqrtf(var + 1e-5f);
                }
            }
            __syncthreads();

            const float* xb = gO + (size_t)(4 * w) * H_ + 4 * lane;
            float muv[4], rsv[4];
            #pragma unroll
            for (int b = 0; b < 4; b++) {
                muv[b] = sMu[4 * w + b];
                rsv[b] = sRs[4 * w + b];
            }

            #pragma unroll 1
            for (int p2 = 0; p2 < 2; p2++) {
                int g0 = 2 * p2, g1 = 2 * p2 + 1;
                const float* W0 = SWH + (size_t)g0 * 8192;
                const float* W1 = SWH + (size_t)g1 * 8192;
                unsigned long long aA[32], aB[32];
                #pragma unroll
                for (int p = 0; p < 32; p++) { aA[p] = 0ull; aB[p] = 0ull; }

                #pragma unroll
                for (int c = 0; c < 8; c++) {
                    float4 g4 = *(const float4*)&SLNG[c * 128 + 4 * lane];
                    float4 b4 = *(const float4*)&SLNB[c * 128 + 4 * lane];
                    ulonglong2 xn[4];
                    #pragma unroll
                    for (int b = 0; b < 4; b++) {
                        float4 x = *(const float4*)(xb + (size_t)b * H_ + c * 128);
                        float mu = muv[b], rs = rsv[b];
                        float4 r;
                        r.x = (x.x - mu) * rs * g4.x + b4.x;
                        r.y = (x.y - mu) * rs * g4.y + b4.y;
                        r.z = (x.z - mu) * rs * g4.z + b4.z;
                        r.w = (x.w - mu) * rs * g4.w + b4.w;
                        xn[b].x = pack2(r.x, r.y);
                        xn[b].y = pack2(r.z, r.w);
                    }
                    #pragma unroll
                    for (int n = 0; n < 8; n++) {
                        ulonglong2 w0 = *(const ulonglong2*)&W0[n * H_ + c * 128 + 4 * lane];
                        ulonglong2 w1 = *(const ulonglong2*)&W1[n * H_ + c * 128 + 4 * lane];
                        #pragma unroll
                        for (int b = 0; b < 4; b++) {
                            fma2(aA[b * 8 + n], xn[b].x, w0.x);
                            fma2(aA[b * 8 + n], xn[b].y, w0.y);
                            fma2(aB[b * 8 + n], xn[b].x, w1.x);
                            fma2(aB[b * 8 + n], xn[b].y, w1.y);
                        }
                    }
                }
                float oA = 0.f, oB = 0.f;
                #pragma unroll
                for (int p = 0; p < 32; p++) {
                    float2 va = unpk2(aA[p]);
                    float2 vb = unpk2(aB[p]);
                    float sa = va.x + va.y, sb2 = vb.x + vb.y;
                    #pragma unroll
                    for (int o = 16; o; o >>= 1) {
                        sa  += __shfl_xor_sync(0xffffffffu, sa,  o);
                        sb2 += __shfl_xor_sync(0xffffffffu, sb2, o);
                    }
                    if (lane == p) { oA = sa; oB = sb2; }
                }
                int bg = 4 * w + (lane >> 3);
                int c  = lane & 7;
                int nA = g0 * H_ + bx * 8 + c;
                int nB = g1 * H_ + bx * 8 + c;
                size_t xrow = ((size_t)bg * S_ + t) * (4 * H_);
                oA += b_hh[nA] + gXp[xrow + nA];
                oB += b_hh[nB] + gXp[xrow + nB];
                sG[g0 * 256 + c * 32 + bg] = oA;
                sG[g1 * 256 + c * 32 + bg] = oB;
            }
            __syncthreads();
            int b = tid & 31, jj = tid >> 5;
            int j2 = bx * 8 + jj;
            float ii = sG[0 * 256 + jj * 32 + b];
            float ff = sG[1 * 256 + jj * 32 + b];
            float gg = sG[2 * 256 + jj * 32 + b];
            float oo = sG[3 * 256 + jj * 32 + b];
            float si = 1.f / (1.f + expf(-ii));
            float sf = 1.f / (1.f + expf(-ff));
            float so = 1.f / (1.f + expf(-oo));
            float cn = sf * gC[b * H_ + j2] + si * tanhf(gg);
            float hn = so * tanhf(cn);
            gC[b * H_ + j2] = cn;
            gH[b * H_ + j2] = hn;
            // store h as bf16 hi/lo for the logits GEMM
            size_t hidx = ((size_t)b * S_ + t) * H_ + j2;
            __nv_bfloat16 hb = __float2bfloat16(hn);
            float hf = __bfloat162float(hb);
            __nv_bfloat16 lb = __float2bfloat16(hn - hf);
            gHallH[hidx] = *(unsigned short*)&hb;
            gHallL[hidx] = *(unsigned short*)&lb;
        }
        grid_bar();
    }
}

// ---------------- orchestration ----------------------------------------------
extern "C" void kernel_launch(void* const* d_in, const int* in_sizes, int n_in,
                              void* d_out, int out_size)
{
    const float* features = (const float*)d_in[0];
    const int*   captions = (const int*)  d_in[1];
    const float* emb      = (const float*)d_in[2];
    const float* q_w      = (const float*)d_in[3];
    const float* k_w      = (const float*)d_in[4];
    const float* v_w      = (const float*)d_in[5];
    const float* in_b     = (const float*)d_in[6];
    const float* out_w    = (const float*)d_in[7];
    const float* out_b    = (const float*)d_in[8];
    const float* h0_w     = (const float*)d_in[9];
    const float* h0_b     = (const float*)d_in[10];
    const float* c0_w     = (const float*)d_in[11];
    const float* c0_b     = (const float*)d_in[12];
    const float* w_ih     = (const float*)d_in[13];
    const float* b_ih     = (const float*)d_in[14];
    const float* w_hh     = (const float*)d_in[15];
    const float* b_hh     = (const float*)d_in[16];
    const float* ln_g     = (const float*)d_in[17];
    const float* ln_b2    = (const float*)d_in[18];
    const float* lin_w    = (const float*)d_in[19];
    const float* lin_b    = (const float*)d_in[20];

    float* sc = nullptr;
    cudaGetSymbolAddress((void**)&sc, g_scratch);
    float* gK    = sc + OFF_K;
    float* gV    = sc + OFF_V;
    float* gMean = sc + OFF_MEAN;
    float* gH    = sc + OFF_H;
    float* gC    = sc + OFF_C;
    float* gQ    = sc + OFF_Q;
    float* gCtx  = sc + OFF_CTX;
    float* gO    = sc + OFF_O;
    float* gSc   = sc + OFF_SC;
    float* gXp   = sc + OFF_XP;
    float* gAd   = sc + OFF_AD;
    unsigned short* gFH  = (unsigned short*)(sc + OFF_FH);
    unsigned short* gFL  = (unsigned short*)(sc + OFF_FL);
    unsigned short* gKWH = (unsigned short*)(sc + OFF_KWH);
    unsigned short* gKWL = (unsigned short*)(sc + OFF_KWL);
    unsigned short* gVWH = (unsigned short*)(sc + OFF_VWH);
    unsigned short* gVWL = (unsigned short*)(sc + OFF_VWL);
    unsigned short* gWIH = (unsigned short*)(sc + OFF_WIH);
    unsigned short* gWIL = (unsigned short*)(sc + OFF_WIL);
    unsigned short* gLWH = (unsigned short*)(sc + OFF_LWH);
    unsigned short* gLWL = (unsigned short*)(sc + OFF_LWL);
    unsigned short* gEBH = (unsigned short*)(sc + OFF_EBH);
    unsigned short* gEBL = (unsigned short*)(sc + OFF_EBL);
    unsigned short* gHLH = (unsigned short*)(sc + OFF_HLH);
    unsigned short* gHLL = (unsigned short*)(sc + OFF_HLL);

    float* out   = (float*)d_out;
    float* preds = out;
    const size_t PRED = (size_t)B_ * S_ * V_;
    bool wa = ((size_t)out_size >= PRED + (size_t)B_ * S_ * NF_);
    float* attnb = wa ? (out + PRED) : gAd;

    const int REC_SMEM = 51200 * 4;   // 200 KB for recurrence
    cudaFuncSetAttribute(recurrence_kernel,
                         cudaFuncAttributeMaxDynamicSharedMemorySize, REC_SMEM);
    cudaFuncSetAttribute(mma_gemm_bf16,
                         cudaFuncAttributeMaxDynamicSharedMemorySize, MMA_SMEM_BYTES);

    // ---- one-time bf16 hi/lo splits ----
    split_bf16<<<(B_ * NF_ * ENC_) / 2048, 256>>>(features, gFH, gFL);
    split_bf16<<<(H_ * ENC_) / 2048, 256>>>(k_w, gKWH, gKWL);
    split_bf16<<<(H_ * ENC_) / 2048, 256>>>(v_w, gVWH, gVWL);
    split_bf16<<<(4 * H_ * ED_) / 2048, 256>>>(w_ih, gWIH, gWIL);
    split_bf16<<<(V_ * H_) / 2048, 256>>>(lin_w, gLWH, gLWL);

    // ---- setup (hoisted) ----
    mean_gelu_kernel<<<dim3(ENC_ / 256, B_), 256>>>(features, gMean);
    gemvM32<<<H_ / 8, 256>>>(gMean, h0_w, h0_b, gH, H_, ENC_);
    gemvM32<<<H_ / 8, 256>>>(gMean, c0_w, c0_b, gC, H_, ENC_);
    mma_gemm_bf16<<<dim3(H_ / 64, (B_ * NF_) / 128), 256, MMA_SMEM_BYTES>>>(
        gFH, gFL, ENC_, gKWH, gKWL, in_b + H_,     gK, H_, ENC_);
    mma_gemm_bf16<<<dim3(H_ / 64, (B_ * NF_) / 128), 256, MMA_SMEM_BYTES>>>(
        gFH, gFL, ENC_, gVWH, gVWL, in_b + 2 * H_, gV, H_, ENC_);
    gather_kernel<<<(B_ * S_ * ED_) / 256, 256>>>(emb, captions, gEBH, gEBL);
    mma_gemm_bf16<<<dim3((4 * H_) / 64, (B_ * S_) / 128), 256, MMA_SMEM_BYTES>>>(
        gEBH, gEBL, ED_, gWIH, gWIL, b_ih, gXp, 4 * H_, ED_);

    // ---- recurrence in one persistent kernel ----
    recurrence_kernel<<<NB_, 256, REC_SMEM>>>(
        q_w, in_b, out_w, out_b, w_hh, b_hh, ln_g, ln_b2,
        gK, gV, gXp, gH, gC, gQ, gSc, gCtx, gO, gHLH, gHLL, attnb);

    // ---- batched logits on tensor cores ----
    mma_gemm_bf16<<<dim3(V_ / 64, (B_ * S_) / 128), 256, MMA_SMEM_BYTES>>>(
        gHLH, gHLL, H_, gLWH, gLWL, lin_b, preds, V_, H_);
}